// round 3
// baseline (speedup 1.0000x reference)
#include <cuda_runtime.h>
#include <math.h>

// ---------------------------------------------------------------------------
// Problem constants
// ---------------------------------------------------------------------------
#define BATCH 256
#define TLEN  512
#define DIN   64
#define HID   128
#define G4    512              // 4*H
#define NCLS  12
#define MROWS (BATCH * TLEN)   // 131072

// ---------------------------------------------------------------------------
// Scratch (device globals; allocation in kernel_launch is forbidden)
// ---------------------------------------------------------------------------
__device__ float g_G0[(size_t)2 * BATCH * TLEN * G4];   // layer0 gate pre-acts  [dir][b][t][g]
__device__ float g_G1[(size_t)2 * BATCH * TLEN * G4];   // layer1 gate pre-acts
__device__ float g_H1[(size_t)BATCH * TLEN * 2 * HID];  // layer0 output (concat f,b) [b][t][256]
__device__ float g_HT[(size_t)2 * BATCH * HID];         // layer1 final hidden  [dir][b][128]

// ---------------------------------------------------------------------------
// Kernel 1/3: gate-input GEMM.
//   G[dir][b][t][g] = sum_k A[b*T+t][k] * W[dir*512+g][k] + bias[dir*512+g]
//   A: [M][KDIM] row-major, W: [1024][KDIM] row-major ("NT" gemm).
//   Tiles of m that lie entirely past len[b] are skipped (values never read).
// ---------------------------------------------------------------------------
template <int KDIM>
__global__ __launch_bounds__(256)
void gate_gemm_kernel(const float* __restrict__ A,
                      const float* __restrict__ W,
                      const float* __restrict__ bias,
                      const int*   __restrict__ lens,
                      float*       __restrict__ G)
{
    const int BM = 64, BN = 64, BK = 16;
    __shared__ float As[BK][BM + 4];
    __shared__ float Ws[BK][BN + 4];

    const int bm = blockIdx.y;
    const int bn = blockIdx.x;
    const int m0 = bm * BM;
    const int n0 = bn * BN;
    const int b  = m0 >> 9;          // 512 rows per batch, 64 | 512 => single b per tile
    const int t0 = m0 & 511;
    if (t0 >= lens[b]) return;       // whole tile is padding

    const int tid = threadIdx.x;
    const int tx  = tid & 15;        // n micro-tile
    const int ty  = tid >> 4;        // m micro-tile

    // loader mapping: each thread loads one float4 of A and one of W per k-slab
    const int lm  = tid >> 2;        // 0..63
    const int lk4 = (tid & 3) * 4;   // 0,4,8,12

    float acc[4][4];
#pragma unroll
    for (int i = 0; i < 4; i++)
#pragma unroll
        for (int j = 0; j < 4; j++) acc[i][j] = 0.f;

    for (int k0 = 0; k0 < KDIM; k0 += BK) {
        float4 av = *(const float4*)(A + (size_t)(m0 + lm) * KDIM + k0 + lk4);
        float4 wv = *(const float4*)(W + (size_t)(n0 + lm) * KDIM + k0 + lk4);
        __syncthreads();
        As[lk4 + 0][lm] = av.x; As[lk4 + 1][lm] = av.y;
        As[lk4 + 2][lm] = av.z; As[lk4 + 3][lm] = av.w;
        Ws[lk4 + 0][lm] = wv.x; Ws[lk4 + 1][lm] = wv.y;
        Ws[lk4 + 2][lm] = wv.z; Ws[lk4 + 3][lm] = wv.w;
        __syncthreads();
#pragma unroll
        for (int kk = 0; kk < BK; kk++) {
            float4 a = *(const float4*)&As[kk][ty * 4];
            float4 w = *(const float4*)&Ws[kk][tx * 4];
            float am[4] = {a.x, a.y, a.z, a.w};
            float wn[4] = {w.x, w.y, w.z, w.w};
#pragma unroll
            for (int i = 0; i < 4; i++)
#pragma unroll
                for (int j = 0; j < 4; j++)
                    acc[i][j] = fmaf(am[i], wn[j], acc[i][j]);
        }
    }

    // epilogue: add bias, scatter to G[dir][b][t][g]
#pragma unroll
    for (int j = 0; j < 4; j++) {
        const int n    = n0 + tx * 4 + j;
        const int dirn = n >> 9;
        const int gg   = n & 511;
        const float bv = bias[n];
#pragma unroll
        for (int i = 0; i < 4; i++) {
            const int m = m0 + ty * 4 + i;
            const int t = m & 511;
            const size_t off = ((((size_t)dirn * BATCH + b) * TLEN) + t) * G4 + gg;
            G[off] = acc[i][j] + bv;
        }
    }
}

// ---------------------------------------------------------------------------
// Kernel 2/4: persistent LSTM recurrence.
//   One CTA per (dir, batch-pair).  512 threads; thread == gate row g.
//   Whh row g: j=0..95 in SMEM (stride 100 floats -> 4-way conflict = bw-optimal
//   for LDS.128), j=96..127 in registers.  h/c/gate buffers in SMEM.
//   Forward dir reads gates at t=s; backward dir at t=len-1-s.
//   write_seq: emit h1[b][t][dir*128+k] (+ zero-fill t>=len).
//   hT      : emit final hidden state [dir][b][128].
// ---------------------------------------------------------------------------
#define WSTRIDE 100
#define LSTM_SMEM_BYTES ((G4 * WSTRIDE + 4 * HID + 2 * G4) * 4)   // 210944

__device__ __forceinline__ float sigm(float x) { return 1.f / (1.f + expf(-x)); }

__global__ __launch_bounds__(512)
void lstm_kernel(const float* __restrict__ G,
                 const float* __restrict__ Whh,   // [2][512][128]
                 const int*   __restrict__ lens,
                 float*       __restrict__ h1,    // may be null
                 float*       __restrict__ hT,    // may be null
                 int write_seq)
{
    extern __shared__ float sm[];
    float* Wsm  = sm;                        // 512*100
    float* hsm0 = sm + G4 * WSTRIDE;         // 128
    float* hsm1 = hsm0 + HID;
    float* csm0 = hsm1 + HID;
    float* csm1 = csm0 + HID;
    float* gsm0 = csm1 + HID;                // 512
    float* gsm1 = gsm0 + G4;

    const int tid  = threadIdx.x;            // gate row g
    const int dir  = blockIdx.x >> 7;
    const int pair = blockIdx.x & 127;
    const int b0   = pair * 2;
    const int b1   = b0 + 1;

    // load weights: 96 cols to smem, 32 cols to registers
    const float4* wrow = (const float4*)(Whh + ((size_t)dir * G4 + tid) * HID);
    float4 wreg[8];
#pragma unroll
    for (int r = 0; r < 8; r++) wreg[r] = wrow[24 + r];
    {
        float4* dst = (float4*)(Wsm + tid * WSTRIDE);
#pragma unroll
        for (int r = 0; r < 24; r++) dst[r] = wrow[r];
    }
    if (tid < HID) { hsm0[tid] = 0.f; hsm1[tid] = 0.f; csm0[tid] = 0.f; csm1[tid] = 0.f; }

    const int len0 = lens[b0];
    const int len1 = lens[b1];
    const int Tmax = (len0 > len1) ? len0 : len1;
    const float* Gb0 = G + (((size_t)dir * BATCH + b0) << 18);   // *T*G4
    const float* Gb1 = G + (((size_t)dir * BATCH + b1) << 18);

    __syncthreads();

    for (int s = 0; s < Tmax; s++) {
        // issue gate-input loads early (consumed at the end of the dot products)
        int t0 = dir ? (len0 - 1 - s) : s; if (t0 < 0) t0 = 0;
        int t1 = dir ? (len1 - 1 - s) : s; if (t1 < 0) t1 = 0;
        const float gv0 = Gb0[(size_t)t0 * G4 + tid];
        const float gv1 = Gb1[(size_t)t1 * G4 + tid];

        float acc0 = 0.f, acc1 = 0.f;
        const float4* w4  = (const float4*)(Wsm + tid * WSTRIDE);
        const float4* h04 = (const float4*)hsm0;
        const float4* h14 = (const float4*)hsm1;
#pragma unroll
        for (int j = 0; j < 24; j++) {
            float4 w = w4[j];
            float4 a = h04[j];
            float4 c = h14[j];
            acc0 = fmaf(w.x, a.x, acc0); acc1 = fmaf(w.x, c.x, acc1);
            acc0 = fmaf(w.y, a.y, acc0); acc1 = fmaf(w.y, c.y, acc1);
            acc0 = fmaf(w.z, a.z, acc0); acc1 = fmaf(w.z, c.z, acc1);
            acc0 = fmaf(w.w, a.w, acc0); acc1 = fmaf(w.w, c.w, acc1);
        }
#pragma unroll
        for (int r = 0; r < 8; r++) {
            float4 w = wreg[r];
            float4 a = h04[24 + r];
            float4 c = h14[24 + r];
            acc0 = fmaf(w.x, a.x, acc0); acc1 = fmaf(w.x, c.x, acc1);
            acc0 = fmaf(w.y, a.y, acc0); acc1 = fmaf(w.y, c.y, acc1);
            acc0 = fmaf(w.z, a.z, acc0); acc1 = fmaf(w.z, c.z, acc1);
            acc0 = fmaf(w.w, a.w, acc0); acc1 = fmaf(w.w, c.w, acc1);
        }
        gsm0[tid] = acc0 + gv0;
        gsm1[tid] = acc1 + gv1;
        __syncthreads();

        if (tid < 2 * HID) {
            const int nb  = tid >> 7;
            const int k   = tid & 127;
            const int len = nb ? len1 : len0;
            if (s < len) {
                float* gs = nb ? gsm1 : gsm0;
                float* hs = nb ? hsm1 : hsm0;
                float* cs = nb ? csm1 : csm0;
                const float ig = sigm(gs[k]);
                const float fg = sigm(gs[HID + k]);
                const float gg = tanhf(gs[2 * HID + k]);
                const float og = sigm(gs[3 * HID + k]);
                const float cn = fmaf(fg, cs[k], ig * gg);
                const float hn = og * tanhf(cn);
                cs[k] = cn;
                hs[k] = hn;
                if (write_seq) {
                    const int b = nb ? b1 : b0;
                    const int t = dir ? (len - 1 - s) : s;
                    h1[((size_t)b * TLEN + t) * (2 * HID) + dir * HID + k] = hn;
                }
            }
        }
        __syncthreads();
    }

    if (hT && tid < 2 * HID) {
        const int nb = tid >> 7;
        const int k  = tid & 127;
        const int b  = nb ? b1 : b0;
        const float* hs = nb ? hsm1 : hsm0;
        hT[((size_t)dir * BATCH + b) * HID + k] = hs[k];
    }

    if (write_seq) {
        // zero-fill padded region (reference masks hs to zero at t >= len)
#pragma unroll
        for (int nb = 0; nb < 2; nb++) {
            const int b   = nb ? b1 : b0;
            const int len = nb ? len1 : len0;
            const int ntail = (TLEN - len) * HID;
            for (int idx = tid; idx < ntail; idx += 512) {
                const int t = len + (idx >> 7);
                const int k = idx & 127;
                h1[((size_t)b * TLEN + t) * (2 * HID) + dir * HID + k] = 0.f;
            }
        }
    }
}

// ---------------------------------------------------------------------------
// Kernel 5: FC + log_softmax.  h = concat([hT_backward, hT_forward]).
// ---------------------------------------------------------------------------
__global__ __launch_bounds__(32)
void fc_kernel(const float* __restrict__ HT,    // [2][256][128] (dir0=fwd, dir1=bwd)
               const float* __restrict__ Wfc,   // [12][256]
               const float* __restrict__ bfc,   // [12]
               float*       __restrict__ out)   // [256][12]
{
    const int b = blockIdx.x;
    const int c = threadIdx.x;
    float acc = 0.f;
    if (c < NCLS) {
        acc = bfc[c];
        const float* hb = HT + ((size_t)BATCH + b) * HID;  // dir1 = backward (first half)
        const float* hf = HT + (size_t)b * HID;            // dir0 = forward  (second half)
        const float* w  = Wfc + c * (2 * HID);
#pragma unroll 4
        for (int k = 0; k < HID; k++) acc = fmaf(w[k], hb[k], acc);
#pragma unroll 4
        for (int k = 0; k < HID; k++) acc = fmaf(w[HID + k], hf[k], acc);
    }
    float mx = (c < NCLS) ? acc : -3.4e38f;
#pragma unroll
    for (int o = 16; o; o >>= 1) mx = fmaxf(mx, __shfl_xor_sync(0xffffffffu, mx, o));
    float e = (c < NCLS) ? expf(acc - mx) : 0.f;
    float ssum = e;
#pragma unroll
    for (int o = 16; o; o >>= 1) ssum += __shfl_xor_sync(0xffffffffu, ssum, o);
    if (c < NCLS) out[b * NCLS + c] = acc - mx - logf(ssum);
}

// ---------------------------------------------------------------------------
// Launch
// ---------------------------------------------------------------------------
extern "C" void kernel_launch(void* const* d_in, const int* in_sizes, int n_in,
                              void* d_out, int out_size)
{
    const float* X    = (const float*)d_in[0];
    const int*   lens = (const int*)  d_in[1];
    const float* Wih0 = (const float*)d_in[2];
    const float* Whh0 = (const float*)d_in[3];
    const float* b0   = (const float*)d_in[4];
    const float* Wih1 = (const float*)d_in[5];
    const float* Whh1 = (const float*)d_in[6];
    const float* b1   = (const float*)d_in[7];
    const float* Wfc  = (const float*)d_in[8];
    const float* bfc  = (const float*)d_in[9];
    float* out = (float*)d_out;

    float *G0, *G1, *H1, *HT;
    cudaGetSymbolAddress((void**)&G0, g_G0);
    cudaGetSymbolAddress((void**)&G1, g_G1);
    cudaGetSymbolAddress((void**)&H1, g_H1);
    cudaGetSymbolAddress((void**)&HT, g_HT);

    cudaFuncSetAttribute(lstm_kernel, cudaFuncAttributeMaxDynamicSharedMemorySize,
                         LSTM_SMEM_BYTES);

    dim3 gemm_grid(16, MROWS / 64);   // N-tiles x M-tiles

    // layer 0: input gates, then bidirectional recurrence -> H1
    gate_gemm_kernel<DIN><<<gemm_grid, 256>>>(X, Wih0, b0, lens, G0);
    lstm_kernel<<<256, 512, LSTM_SMEM_BYTES>>>(G0, Whh0, lens, H1, nullptr, 1);

    // layer 1: input gates over H1, recurrence -> final hiddens only
    gate_gemm_kernel<2 * HID><<<gemm_grid, 256>>>(H1, Wih1, b1, lens, G1);
    lstm_kernel<<<256, 512, LSTM_SMEM_BYTES>>>(G1, Whh1, lens, nullptr, HT, 0);

    // classifier head
    fc_kernel<<<BATCH, 32>>>(HT, Wfc, bfc, out);
}

// round 4
// speedup vs baseline: 1.3009x; 1.3009x over previous
#include <cuda_runtime.h>
#include <math.h>

// ---------------------------------------------------------------------------
// Problem constants
// ---------------------------------------------------------------------------
#define BATCH 256
#define TLEN  512
#define DIN   64
#define HID   128
#define G4    512              // 4*H
#define NCLS  12
#define MROWS (BATCH * TLEN)   // 131072

typedef unsigned long long ull;

// ---- packed f32x2 helpers (sm_100+ only; ptxas never auto-fuses these) ----
__device__ __forceinline__ ull pack2(float lo, float hi) {
    ull r; asm("mov.b64 %0, {%1, %2};" : "=l"(r) : "f"(lo), "f"(hi)); return r;
}
__device__ __forceinline__ void unpack2(ull v, float& lo, float& hi) {
    asm("mov.b64 {%0, %1}, %2;" : "=f"(lo), "=f"(hi) : "l"(v));
}
__device__ __forceinline__ ull ffma2(ull a, ull b, ull c) {
    ull d; asm("fma.rn.f32x2 %0, %1, %2, %3;" : "=l"(d) : "l"(a), "l"(b), "l"(c));
    return d;
}
__device__ __forceinline__ float hsum2(ull v) {
    float lo, hi; unpack2(v, lo, hi); return lo + hi;
}

// ---------------------------------------------------------------------------
// Scratch (device globals; allocation in kernel_launch is forbidden)
// ---------------------------------------------------------------------------
__device__ float g_G0[(size_t)2 * BATCH * TLEN * G4];   // layer0 gate pre-acts [dir][b][t][g]
__device__ float g_G1[(size_t)2 * BATCH * TLEN * G4];   // layer1 gate pre-acts
__device__ float g_H1[(size_t)BATCH * TLEN * 2 * HID];  // layer0 output [b][t][256]
__device__ float g_HT[(size_t)2 * BATCH * HID];         // layer1 final hidden [dir][b][128]

// ---------------------------------------------------------------------------
// Gate-input GEMM (NT):  G[dir][b][t][g] = A[m][:]·W[n][:] + bias[n]
//   BM=128, BN=64, BK=16, 256 threads, 8x4 micro-tile, FFMA2 on m-pairs.
//   Tiles entirely past len[b] are skipped (their values are never read).
// ---------------------------------------------------------------------------
template <int KDIM>
__global__ __launch_bounds__(256)
void gate_gemm_kernel(const float* __restrict__ A,
                      const float* __restrict__ W,
                      const float* __restrict__ bias,
                      const int*   __restrict__ lens,
                      float*       __restrict__ G)
{
    const int BM = 128, BN = 64, BK = 16;
    __shared__ __align__(16) float As[BK][BM + 4];
    __shared__ __align__(16) float Ws[BK][BN + 4];

    const int m0 = blockIdx.y * BM;
    const int n0 = blockIdx.x * BN;
    const int b  = m0 >> 9;          // 512 rows per batch; 128 | 512
    const int t0 = m0 & 511;
    if (t0 >= lens[b]) return;       // whole tile is padding (uniform exit)

    const int tid = threadIdx.x;
    const int tx  = tid & 15;        // n group (4 cols)
    const int ty  = tid >> 4;        // m group (8 rows)

    // loaders
    const int lmA = tid >> 1;        // 0..127
    const int kA  = (tid & 1) * 8;   // 0 or 8
    const int lmW = tid >> 2;        // 0..63
    const int kW  = (tid & 3) * 4;

    ull acc[4][4];
#pragma unroll
    for (int p = 0; p < 4; p++)
#pragma unroll
        for (int j = 0; j < 4; j++) acc[p][j] = 0ull;

    for (int k0 = 0; k0 < KDIM; k0 += BK) {
        float4 a0 = *(const float4*)(A + (size_t)(m0 + lmA) * KDIM + k0 + kA);
        float4 a1 = *(const float4*)(A + (size_t)(m0 + lmA) * KDIM + k0 + kA + 4);
        float4 wv = *(const float4*)(W + (size_t)(n0 + lmW) * KDIM + k0 + kW);
        __syncthreads();
        As[kA + 0][lmA] = a0.x; As[kA + 1][lmA] = a0.y;
        As[kA + 2][lmA] = a0.z; As[kA + 3][lmA] = a0.w;
        As[kA + 4][lmA] = a1.x; As[kA + 5][lmA] = a1.y;
        As[kA + 6][lmA] = a1.z; As[kA + 7][lmA] = a1.w;
        Ws[kW + 0][lmW] = wv.x; Ws[kW + 1][lmW] = wv.y;
        Ws[kW + 2][lmW] = wv.z; Ws[kW + 3][lmW] = wv.w;
        __syncthreads();
#pragma unroll
        for (int kk = 0; kk < BK; kk++) {
            ulonglong2 a01 = *(const ulonglong2*)&As[kk][ty * 8];
            ulonglong2 a23 = *(const ulonglong2*)&As[kk][ty * 8 + 4];
            float4 w = *(const float4*)&Ws[kk][tx * 4];
            ull b0 = pack2(w.x, w.x), b1 = pack2(w.y, w.y);
            ull b2 = pack2(w.z, w.z), b3 = pack2(w.w, w.w);
            acc[0][0] = ffma2(a01.x, b0, acc[0][0]);
            acc[0][1] = ffma2(a01.x, b1, acc[0][1]);
            acc[0][2] = ffma2(a01.x, b2, acc[0][2]);
            acc[0][3] = ffma2(a01.x, b3, acc[0][3]);
            acc[1][0] = ffma2(a01.y, b0, acc[1][0]);
            acc[1][1] = ffma2(a01.y, b1, acc[1][1]);
            acc[1][2] = ffma2(a01.y, b2, acc[1][2]);
            acc[1][3] = ffma2(a01.y, b3, acc[1][3]);
            acc[2][0] = ffma2(a23.x, b0, acc[2][0]);
            acc[2][1] = ffma2(a23.x, b1, acc[2][1]);
            acc[2][2] = ffma2(a23.x, b2, acc[2][2]);
            acc[2][3] = ffma2(a23.x, b3, acc[2][3]);
            acc[3][0] = ffma2(a23.y, b0, acc[3][0]);
            acc[3][1] = ffma2(a23.y, b1, acc[3][1]);
            acc[3][2] = ffma2(a23.y, b2, acc[3][2]);
            acc[3][3] = ffma2(a23.y, b3, acc[3][3]);
        }
    }

    // epilogue: add bias, scatter to G[dir][b][t][g] as float4 along g
    const int n    = n0 + tx * 4;
    const int dirn = n >> 9;
    const int gg   = n & 511;
    const float4 bv = *(const float4*)(bias + n);
#pragma unroll
    for (int p = 0; p < 4; p++) {
        float lo0, hi0, lo1, hi1, lo2, hi2, lo3, hi3;
        unpack2(acc[p][0], lo0, hi0); unpack2(acc[p][1], lo1, hi1);
        unpack2(acc[p][2], lo2, hi2); unpack2(acc[p][3], lo3, hi3);
        const int m = m0 + ty * 8 + 2 * p;
        const int t = m & 511;
        const size_t base = ((((size_t)dirn * BATCH + b) * TLEN) + t) * G4 + gg;
        float4 o0 = {lo0 + bv.x, lo1 + bv.y, lo2 + bv.z, lo3 + bv.w};
        float4 o1 = {hi0 + bv.x, hi1 + bv.y, hi2 + bv.z, hi3 + bv.w};
        *(float4*)&G[base]      = o0;
        *(float4*)&G[base + G4] = o1;
    }
}

// ---------------------------------------------------------------------------
// Persistent LSTM recurrence. One CTA per (dir, 4-batch group) -> 128 CTAs,
// a single balanced wave. 512 threads; thread == gate row g.
//   Whh row g: j=0..63 in SMEM (stride 68 floats -> LDS.128 wavefront floor),
//   j=64..127 packed f32x2 in registers.
//   Dot products use j-packed FFMA2 (halves summed once per step).
//   Pointwise update: thread tid -> (nb=tid>>7, k=tid&127); c lives in a reg.
// ---------------------------------------------------------------------------
#define WSTRIDE 68
#define LSTM_SMEM_BYTES ((G4 * WSTRIDE + 4 * HID + 4 * G4) * 4)   // 149504

__device__ __forceinline__ float sigm(float x) { return 1.f / (1.f + expf(-x)); }

__global__ __launch_bounds__(512)
void lstm_kernel(const float* __restrict__ G,
                 const float* __restrict__ Whh,   // [2][512][128]
                 const int*   __restrict__ lens,
                 float*       __restrict__ h1,    // may be null
                 float*       __restrict__ hT,    // may be null
                 int write_seq)
{
    extern __shared__ float sm[];
    float* Wsm = sm;                          // 512 * 68
    float* hsm = sm + G4 * WSTRIDE;           // 4 * 128 (per-batch h, contiguous)
    float* gsm = hsm + 4 * HID;               // 4 * 512

    const int tid = threadIdx.x;              // gate row g
    const int dir = blockIdx.x >> 6;
    const int bb  = (blockIdx.x & 63) * 4;    // first of 4 batches

    // ---- load Whh row: j=0..63 -> smem, j=64..127 -> packed regs ----
    const float4* wrow = (const float4*)(Whh + ((size_t)dir * G4 + tid) * HID);
    ull wreg[32];
#pragma unroll
    for (int r = 0; r < 16; r++) {
        float4 w = wrow[16 + r];
        wreg[2 * r]     = pack2(w.x, w.y);
        wreg[2 * r + 1] = pack2(w.z, w.w);
    }
    {
        float4* dst = (float4*)(Wsm + tid * WSTRIDE);
#pragma unroll
        for (int r = 0; r < 16; r++) dst[r] = wrow[r];
    }
    hsm[tid] = 0.f;                           // zero all 4x128 h entries
    float cst = 0.f;                          // this thread's cell state
    const int nb_u = tid >> 7;
    const int k_u  = tid & 127;

    int len[4];
#pragma unroll
    for (int q = 0; q < 4; q++) len[q] = lens[bb + q];
    int Tmax = max(max(len[0], len[1]), max(len[2], len[3]));
    const int mylen = len[nb_u];

    const float* Gb[4];
#pragma unroll
    for (int q = 0; q < 4; q++)
        Gb[q] = G + (((size_t)dir * BATCH + bb + q) << 18);   // * T * G4

    __syncthreads();

    for (int s = 0; s < Tmax; s++) {
        // gate-input loads (independent; overlap the dot products)
        float gv[4];
#pragma unroll
        for (int q = 0; q < 4; q++) {
            int t = dir ? (len[q] - 1 - s) : s;
            t = t < 0 ? 0 : t;
            gv[q] = Gb[q][(size_t)t * G4 + tid];
        }

        ull acc0 = 0, acc1 = 0, acc2 = 0, acc3 = 0;
        const ulonglong2* W2 = (const ulonglong2*)(Wsm + tid * WSTRIDE);
        const ulonglong2* H0 = (const ulonglong2*)(hsm);
        const ulonglong2* H1 = (const ulonglong2*)(hsm + HID);
        const ulonglong2* H2 = (const ulonglong2*)(hsm + 2 * HID);
        const ulonglong2* H3 = (const ulonglong2*)(hsm + 3 * HID);
#pragma unroll
        for (int q = 0; q < 16; q++) {        // j = 0..63 (W from smem)
            ulonglong2 w = W2[q];
            ulonglong2 a = H0[q], b = H1[q], c = H2[q], d = H3[q];
            acc0 = ffma2(w.x, a.x, acc0); acc0 = ffma2(w.y, a.y, acc0);
            acc1 = ffma2(w.x, b.x, acc1); acc1 = ffma2(w.y, b.y, acc1);
            acc2 = ffma2(w.x, c.x, acc2); acc2 = ffma2(w.y, c.y, acc2);
            acc3 = ffma2(w.x, d.x, acc3); acc3 = ffma2(w.y, d.y, acc3);
        }
#pragma unroll
        for (int q = 0; q < 16; q++) {        // j = 64..127 (W from regs)
            ull w0 = wreg[2 * q], w1 = wreg[2 * q + 1];
            ulonglong2 a = H0[16 + q], b = H1[16 + q], c = H2[16 + q], d = H3[16 + q];
            acc0 = ffma2(w0, a.x, acc0); acc0 = ffma2(w1, a.y, acc0);
            acc1 = ffma2(w0, b.x, acc1); acc1 = ffma2(w1, b.y, acc1);
            acc2 = ffma2(w0, c.x, acc2); acc2 = ffma2(w1, c.y, acc2);
            acc3 = ffma2(w0, d.x, acc3); acc3 = ffma2(w1, d.y, acc3);
        }
        gsm[0 * G4 + tid] = hsum2(acc0) + gv[0];
        gsm[1 * G4 + tid] = hsum2(acc1) + gv[1];
        gsm[2 * G4 + tid] = hsum2(acc2) + gv[2];
        gsm[3 * G4 + tid] = hsum2(acc3) + gv[3];
        __syncthreads();

        if (s < mylen) {
            const float* gs = gsm + nb_u * G4;
            const float ig = sigm(gs[k_u]);
            const float fg = sigm(gs[HID + k_u]);
            const float gg = tanhf(gs[2 * HID + k_u]);
            const float og = sigm(gs[3 * HID + k_u]);
            cst = fmaf(fg, cst, ig * gg);
            const float hn = og * tanhf(cst);
            hsm[tid] = hn;
            if (write_seq) {
                const int b = bb + nb_u;
                const int t = dir ? (mylen - 1 - s) : s;
                h1[((size_t)b * TLEN + t) * (2 * HID) + dir * HID + k_u] = hn;
            }
        }
        __syncthreads();
    }

    if (hT)
        hT[((size_t)dir * BATCH + bb + nb_u) * HID + k_u] = hsm[tid];

    if (write_seq) {
        // zero-fill padded region (reference masks hs to zero at t >= len)
#pragma unroll
        for (int q = 0; q < 4; q++) {
            const int b  = bb + q;
            const int lq = len[q];
            const int ntail = (TLEN - lq) * HID;
            for (int idx = tid; idx < ntail; idx += 512) {
                const int t = lq + (idx >> 7);
                const int k = idx & 127;
                h1[((size_t)b * TLEN + t) * (2 * HID) + dir * HID + k] = 0.f;
            }
        }
    }
}

// ---------------------------------------------------------------------------
// FC + log_softmax.  h = concat([hT_backward, hT_forward]).
// ---------------------------------------------------------------------------
__global__ __launch_bounds__(32)
void fc_kernel(const float* __restrict__ HT,    // [2][256][128] (dir0=fwd, dir1=bwd)
               const float* __restrict__ Wfc,   // [12][256]
               const float* __restrict__ bfc,   // [12]
               float*       __restrict__ out)   // [256][12]
{
    const int b = blockIdx.x;
    const int c = threadIdx.x;
    float acc = 0.f;
    if (c < NCLS) {
        acc = bfc[c];
        const float* hb = HT + ((size_t)BATCH + b) * HID;  // dir1 = backward (first half)
        const float* hf = HT + (size_t)b * HID;            // dir0 = forward  (second half)
        const float* w  = Wfc + c * (2 * HID);
#pragma unroll 4
        for (int k = 0; k < HID; k++) acc = fmaf(w[k], hb[k], acc);
#pragma unroll 4
        for (int k = 0; k < HID; k++) acc = fmaf(w[HID + k], hf[k], acc);
    }
    float mx = (c < NCLS) ? acc : -3.4e38f;
#pragma unroll
    for (int o = 16; o; o >>= 1) mx = fmaxf(mx, __shfl_xor_sync(0xffffffffu, mx, o));
    float e = (c < NCLS) ? expf(acc - mx) : 0.f;
    float ssum = e;
#pragma unroll
    for (int o = 16; o; o >>= 1) ssum += __shfl_xor_sync(0xffffffffu, ssum, o);
    if (c < NCLS) out[b * NCLS + c] = acc - mx - logf(ssum);
}

// ---------------------------------------------------------------------------
// Launch
// ---------------------------------------------------------------------------
extern "C" void kernel_launch(void* const* d_in, const int* in_sizes, int n_in,
                              void* d_out, int out_size)
{
    const float* X    = (const float*)d_in[0];
    const int*   lens = (const int*)  d_in[1];
    const float* Wih0 = (const float*)d_in[2];
    const float* Whh0 = (const float*)d_in[3];
    const float* b0   = (const float*)d_in[4];
    const float* Wih1 = (const float*)d_in[5];
    const float* Whh1 = (const float*)d_in[6];
    const float* b1   = (const float*)d_in[7];
    const float* Wfc  = (const float*)d_in[8];
    const float* bfc  = (const float*)d_in[9];
    float* out = (float*)d_out;

    float *G0, *G1, *H1, *HT;
    cudaGetSymbolAddress((void**)&G0, g_G0);
    cudaGetSymbolAddress((void**)&G1, g_G1);
    cudaGetSymbolAddress((void**)&H1, g_H1);
    cudaGetSymbolAddress((void**)&HT, g_HT);

    cudaFuncSetAttribute(lstm_kernel, cudaFuncAttributeMaxDynamicSharedMemorySize,
                         LSTM_SMEM_BYTES);

    dim3 gemm_grid(1024 / 64, MROWS / 128);   // N-tiles x M-tiles

    // layer 0: input gates, then bidirectional recurrence -> H1
    gate_gemm_kernel<DIN><<<gemm_grid, 256>>>(X, Wih0, b0, lens, G0);
    lstm_kernel<<<128, 512, LSTM_SMEM_BYTES>>>(G0, Whh0, lens, H1, nullptr, 1);

    // layer 1: input gates over H1, recurrence -> final hiddens only
    gate_gemm_kernel<2 * HID><<<gemm_grid, 256>>>(H1, Whh1 ? Wih1 : Wih1, b1, lens, G1);
    lstm_kernel<<<128, 512, LSTM_SMEM_BYTES>>>(G1, Whh1, lens, nullptr, HT, 0);

    // classifier head
    fc_kernel<<<BATCH, 32>>>(HT, Wfc, bfc, out);
}

// round 5
// speedup vs baseline: 1.5123x; 1.1624x over previous
#include <cuda_runtime.h>
#include <math.h>

// ---------------------------------------------------------------------------
// Problem constants
// ---------------------------------------------------------------------------
#define BATCH 256
#define TLEN  512
#define DIN   64
#define HID   128
#define G4    512              // 4*H
#define NCLS  12
#define MROWS (BATCH * TLEN)   // 131072

typedef unsigned long long ull;

// ---- packed f32x2 helpers (lstm recurrence) ----
__device__ __forceinline__ ull pack2(float lo, float hi) {
    ull r; asm("mov.b64 %0, {%1, %2};" : "=l"(r) : "f"(lo), "f"(hi)); return r;
}
__device__ __forceinline__ void unpack2(ull v, float& lo, float& hi) {
    asm("mov.b64 {%0, %1}, %2;" : "=f"(lo), "=f"(hi) : "l"(v));
}
__device__ __forceinline__ ull ffma2(ull a, ull b, ull c) {
    ull d; asm("fma.rn.f32x2 %0, %1, %2, %3;" : "=l"(d) : "l"(a), "l"(b), "l"(c));
    return d;
}
__device__ __forceinline__ float hsum2(ull v) {
    float lo, hi; unpack2(v, lo, hi); return lo + hi;
}

// ---- tf32 mma helpers ----
__device__ __forceinline__ unsigned cvt_tf32(float x) {
    unsigned u; asm("cvt.rna.tf32.f32 %0, %1;" : "=r"(u) : "f"(x)); return u;
}
__device__ __forceinline__ void mma_tf32(float d[4], const unsigned a[4],
                                         unsigned b0, unsigned b1) {
    asm("mma.sync.aligned.m16n8k8.row.col.f32.tf32.tf32.f32 "
        "{%0,%1,%2,%3},{%4,%5,%6,%7},{%8,%9},{%0,%1,%2,%3};"
        : "+f"(d[0]), "+f"(d[1]), "+f"(d[2]), "+f"(d[3])
        : "r"(a[0]), "r"(a[1]), "r"(a[2]), "r"(a[3]), "r"(b0), "r"(b1));
}

// ---------------------------------------------------------------------------
// Scratch (device globals; allocation in kernel_launch is forbidden)
// ---------------------------------------------------------------------------
__device__ float g_G0[(size_t)2 * BATCH * TLEN * G4];   // layer0 gate pre-acts [dir][b][t][g]
__device__ float g_G1[(size_t)2 * BATCH * TLEN * G4];   // layer1 gate pre-acts
__device__ float g_H1[(size_t)BATCH * TLEN * 2 * HID];  // layer0 output [b][t][256]
__device__ float g_HT[(size_t)2 * BATCH * HID];         // layer1 final hidden [dir][b][128]

// ---------------------------------------------------------------------------
// Gate-input GEMM on tensor cores (tf32 mma.sync m16n8k8, "NT" layout):
//   G[dir][b][t][g] = A[m][:] . W[n][:] + bias[n]
//   CTA tile 128x128, BK=32, 256 threads = 8 warps (4m x 2n), warp tile 32x64.
//   Fragments fed from +4-padded smem (conflict-free scalar LDS).
//   M-tiles entirely past len[b] are skipped (values never read downstream).
// ---------------------------------------------------------------------------
template <int KDIM>
__global__ __launch_bounds__(256, 2)
void gate_gemm_tc(const float* __restrict__ A,
                  const float* __restrict__ W,
                  const float* __restrict__ bias,
                  const int*   __restrict__ lens,
                  float*       __restrict__ G)
{
    constexpr int BM = 128, BN = 128, BK = 32, LDSA = BK + 4;   // 36
    __shared__ unsigned As[BM * LDSA];
    __shared__ unsigned Ws[BN * LDSA];

    const int m0 = blockIdx.y * BM;
    const int n0 = blockIdx.x * BN;
    const int b  = m0 >> 9;                 // 128 | 512 -> one batch per tile
    if ((m0 & 511) >= lens[b]) return;      // whole tile is padding (uniform exit)

    const int tid  = threadIdx.x;
    const int lane = tid & 31;
    const int w    = tid >> 5;
    const int g    = lane >> 2;             // groupID
    const int t    = lane & 3;              // threadID_in_group
    const int wm   = w >> 1;                // 0..3  (m offset 32 each)
    const int wn   = w & 1;                 // 0..1  (n offset 64 each)

    // global->smem loader mapping: thread covers half a 32-float row
    const int lrow = tid >> 1;
    const int lcol = (tid & 1) * 16;

    float d[2][8][4];
#pragma unroll
    for (int mi = 0; mi < 2; mi++)
#pragma unroll
        for (int ni = 0; ni < 8; ni++)
#pragma unroll
            for (int c = 0; c < 4; c++) d[mi][ni][c] = 0.f;

    for (int k0 = 0; k0 < KDIM; k0 += BK) {
        // prefetch global
        float4 av[4], wv[4];
        const float* Ap = A + (size_t)(m0 + lrow) * KDIM + k0 + lcol;
        const float* Wp = W + (size_t)(n0 + lrow) * KDIM + k0 + lcol;
#pragma unroll
        for (int i = 0; i < 4; i++) {
            av[i] = *(const float4*)(Ap + 4 * i);
            wv[i] = *(const float4*)(Wp + 4 * i);
        }
        __syncthreads();
#pragma unroll
        for (int i = 0; i < 4; i++) {
            uint4 ua = { cvt_tf32(av[i].x), cvt_tf32(av[i].y),
                         cvt_tf32(av[i].z), cvt_tf32(av[i].w) };
            uint4 uw = { cvt_tf32(wv[i].x), cvt_tf32(wv[i].y),
                         cvt_tf32(wv[i].z), cvt_tf32(wv[i].w) };
            *(uint4*)&As[lrow * LDSA + lcol + 4 * i] = ua;
            *(uint4*)&Ws[lrow * LDSA + lcol + 4 * i] = uw;
        }
        __syncthreads();

#pragma unroll
        for (int kk = 0; kk < BK; kk += 8) {
            unsigned a[2][4];
#pragma unroll
            for (int mi = 0; mi < 2; mi++) {
                const int r = wm * 32 + mi * 16;
                a[mi][0] = As[(r + g)     * LDSA + kk + t];
                a[mi][1] = As[(r + g + 8) * LDSA + kk + t];
                a[mi][2] = As[(r + g)     * LDSA + kk + t + 4];
                a[mi][3] = As[(r + g + 8) * LDSA + kk + t + 4];
            }
#pragma unroll
            for (int ni = 0; ni < 8; ni++) {
                const int c = wn * 64 + ni * 8;
                const unsigned b0 = Ws[(c + g) * LDSA + kk + t];
                const unsigned b1 = Ws[(c + g) * LDSA + kk + t + 4];
                mma_tf32(d[0][ni], a[0], b0, b1);
                mma_tf32(d[1][ni], a[1], b0, b1);
            }
        }
    }

    // epilogue: +bias, scatter to G[dir][b][t][g] as float2 (cols 2t, 2t+1)
#pragma unroll
    for (int ni = 0; ni < 8; ni++) {
        const int col  = n0 + wn * 64 + ni * 8 + 2 * t;
        const int dirn = col >> 9;
        const int gg   = col & 511;
        const float2 bv = *(const float2*)(bias + col);
#pragma unroll
        for (int mi = 0; mi < 2; mi++) {
            const int m  = m0 + wm * 32 + mi * 16 + g;
            const int tt = m & 511;
            const size_t base = ((((size_t)dirn * BATCH + b) * TLEN) + tt) * G4 + gg;
            float2 v0 = { d[mi][ni][0] + bv.x, d[mi][ni][1] + bv.y };
            float2 v1 = { d[mi][ni][2] + bv.x, d[mi][ni][3] + bv.y };
            *(float2*)&G[base]              = v0;   // row m
            *(float2*)&G[base + 8 * (size_t)G4] = v1;   // row m+8
        }
    }
}

// ---------------------------------------------------------------------------
// Persistent LSTM recurrence (fp32, exact). One CTA per (dir, 4-batch group)
// -> 128 CTAs, one balanced wave. 512 threads; thread == gate row g.
//   Whh row: j=0..63 in SMEM (stride 68 -> LDS.128 wavefront floor),
//   j=64..127 packed f32x2 in registers. Gate-input LDGs prefetched 1 step.
// ---------------------------------------------------------------------------
#define WSTRIDE 68
#define LSTM_SMEM_BYTES ((G4 * WSTRIDE + 4 * HID + 4 * G4) * 4)   // 149504

__device__ __forceinline__ float sigm(float x) { return 1.f / (1.f + expf(-x)); }

__global__ __launch_bounds__(512)
void lstm_kernel(const float* __restrict__ G,
                 const float* __restrict__ Whh,   // [2][512][128]
                 const int*   __restrict__ lens,
                 float*       __restrict__ h1,    // may be null
                 float*       __restrict__ hT,    // may be null
                 int write_seq)
{
    extern __shared__ float sm[];
    float* Wsm = sm;                          // 512 * 68
    float* hsm = sm + G4 * WSTRIDE;           // 4 * 128
    float* gsm = hsm + 4 * HID;               // 4 * 512

    const int tid = threadIdx.x;              // gate row g
    const int dir = blockIdx.x >> 6;
    const int bb  = (blockIdx.x & 63) * 4;    // first of 4 batches

    const float4* wrow = (const float4*)(Whh + ((size_t)dir * G4 + tid) * HID);
    ull wreg[32];
#pragma unroll
    for (int r = 0; r < 16; r++) {
        float4 w = wrow[16 + r];
        wreg[2 * r]     = pack2(w.x, w.y);
        wreg[2 * r + 1] = pack2(w.z, w.w);
    }
    {
        float4* dst = (float4*)(Wsm + tid * WSTRIDE);
#pragma unroll
        for (int r = 0; r < 16; r++) dst[r] = wrow[r];
    }
    hsm[tid] = 0.f;
    float cst = 0.f;
    const int nb_u = tid >> 7;
    const int k_u  = tid & 127;

    int len[4];
#pragma unroll
    for (int q = 0; q < 4; q++) len[q] = lens[bb + q];
    const int Tmax  = max(max(len[0], len[1]), max(len[2], len[3]));
    const int mylen = len[nb_u];

    const float* Gbase = G + (((size_t)dir * BATCH + bb) << 18);  // q offset q<<18

    __syncthreads();

    // prefetch gate inputs for s = 0
    float gv[4];
#pragma unroll
    for (int q = 0; q < 4; q++) {
        int t = dir ? (len[q] - 1) : 0;
        gv[q] = Gbase[((size_t)q << 18) + (size_t)t * G4 + tid];
    }

    for (int s = 0; s < Tmax; s++) {
        // prefetch next step's gate inputs (hidden behind the dot products)
        float gvn[4];
        const int sn = (s + 1 < Tmax) ? s + 1 : s;
#pragma unroll
        for (int q = 0; q < 4; q++) {
            int t = dir ? (len[q] - 1 - sn) : sn;
            t = t < 0 ? 0 : t;
            gvn[q] = Gbase[((size_t)q << 18) + (size_t)t * G4 + tid];
        }

        ull acc0 = 0, acc1 = 0, acc2 = 0, acc3 = 0;
        const ulonglong2* W2 = (const ulonglong2*)(Wsm + tid * WSTRIDE);
        const ulonglong2* H0 = (const ulonglong2*)(hsm);
        const ulonglong2* H1 = (const ulonglong2*)(hsm + HID);
        const ulonglong2* H2 = (const ulonglong2*)(hsm + 2 * HID);
        const ulonglong2* H3 = (const ulonglong2*)(hsm + 3 * HID);
#pragma unroll
        for (int q = 0; q < 16; q++) {        // j = 0..63 (W from smem)
            ulonglong2 w = W2[q];
            ulonglong2 a = H0[q], b = H1[q], c = H2[q], d = H3[q];
            acc0 = ffma2(w.x, a.x, acc0); acc0 = ffma2(w.y, a.y, acc0);
            acc1 = ffma2(w.x, b.x, acc1); acc1 = ffma2(w.y, b.y, acc1);
            acc2 = ffma2(w.x, c.x, acc2); acc2 = ffma2(w.y, c.y, acc2);
            acc3 = ffma2(w.x, d.x, acc3); acc3 = ffma2(w.y, d.y, acc3);
        }
#pragma unroll
        for (int q = 0; q < 16; q++) {        // j = 64..127 (W from regs)
            ull w0 = wreg[2 * q], w1 = wreg[2 * q + 1];
            ulonglong2 a = H0[16 + q], b = H1[16 + q], c = H2[16 + q], d = H3[16 + q];
            acc0 = ffma2(w0, a.x, acc0); acc0 = ffma2(w1, a.y, acc0);
            acc1 = ffma2(w0, b.x, acc1); acc1 = ffma2(w1, b.y, acc1);
            acc2 = ffma2(w0, c.x, acc2); acc2 = ffma2(w1, c.y, acc2);
            acc3 = ffma2(w0, d.x, acc3); acc3 = ffma2(w1, d.y, acc3);
        }
        gsm[0 * G4 + tid] = hsum2(acc0) + gv[0];
        gsm[1 * G4 + tid] = hsum2(acc1) + gv[1];
        gsm[2 * G4 + tid] = hsum2(acc2) + gv[2];
        gsm[3 * G4 + tid] = hsum2(acc3) + gv[3];
        __syncthreads();

        if (s < mylen) {
            const float* gs = gsm + nb_u * G4;
            const float ig = sigm(gs[k_u]);
            const float fg = sigm(gs[HID + k_u]);
            const float gg = tanhf(gs[2 * HID + k_u]);
            const float og = sigm(gs[3 * HID + k_u]);
            cst = fmaf(fg, cst, ig * gg);
            const float hn = og * tanhf(cst);
            hsm[tid] = hn;
            if (write_seq) {
                const int b = bb + nb_u;
                const int t = dir ? (mylen - 1 - s) : s;
                h1[((size_t)b * TLEN + t) * (2 * HID) + dir * HID + k_u] = hn;
            }
        }
        __syncthreads();

        gv[0] = gvn[0]; gv[1] = gvn[1]; gv[2] = gvn[2]; gv[3] = gvn[3];
    }

    if (hT)
        hT[((size_t)dir * BATCH + bb + nb_u) * HID + k_u] = hsm[tid];

    if (write_seq) {
        // zero-fill padded region (reference masks hs to zero at t >= len)
#pragma unroll
        for (int q = 0; q < 4; q++) {
            const int b  = bb + q;
            const int lq = len[q];
            const int ntail = (TLEN - lq) * HID;
            for (int idx = tid; idx < ntail; idx += 512) {
                const int t = lq + (idx >> 7);
                const int k = idx & 127;
                h1[((size_t)b * TLEN + t) * (2 * HID) + dir * HID + k] = 0.f;
            }
        }
    }
}

// ---------------------------------------------------------------------------
// FC + log_softmax.  h = concat([hT_backward, hT_forward]).
// ---------------------------------------------------------------------------
__global__ __launch_bounds__(32)
void fc_kernel(const float* __restrict__ HT,    // [2][256][128] (dir0=fwd, dir1=bwd)
               const float* __restrict__ Wfc,   // [12][256]
               const float* __restrict__ bfc,   // [12]
               float*       __restrict__ out)   // [256][12]
{
    const int b = blockIdx.x;
    const int c = threadIdx.x;
    float acc = 0.f;
    if (c < NCLS) {
        acc = bfc[c];
        const float* hb = HT + ((size_t)BATCH + b) * HID;  // dir1 = backward (first half)
        const float* hf = HT + (size_t)b * HID;            // dir0 = forward  (second half)
        const float* w  = Wfc + c * (2 * HID);
#pragma unroll 4
        for (int k = 0; k < HID; k++) acc = fmaf(w[k], hb[k], acc);
#pragma unroll 4
        for (int k = 0; k < HID; k++) acc = fmaf(w[HID + k], hf[k], acc);
    }
    float mx = (c < NCLS) ? acc : -3.4e38f;
#pragma unroll
    for (int o = 16; o; o >>= 1) mx = fmaxf(mx, __shfl_xor_sync(0xffffffffu, mx, o));
    float e = (c < NCLS) ? expf(acc - mx) : 0.f;
    float ssum = e;
#pragma unroll
    for (int o = 16; o; o >>= 1) ssum += __shfl_xor_sync(0xffffffffu, ssum, o);
    if (c < NCLS) out[b * NCLS + c] = acc - mx - logf(ssum);
}

// ---------------------------------------------------------------------------
// Launch
// ---------------------------------------------------------------------------
extern "C" void kernel_launch(void* const* d_in, const int* in_sizes, int n_in,
                              void* d_out, int out_size)
{
    const float* X    = (const float*)d_in[0];
    const int*   lens = (const int*)  d_in[1];
    const float* Wih0 = (const float*)d_in[2];
    const float* Whh0 = (const float*)d_in[3];
    const float* b0   = (const float*)d_in[4];
    const float* Wih1 = (const float*)d_in[5];
    const float* Whh1 = (const float*)d_in[6];
    const float* b1   = (const float*)d_in[7];
    const float* Wfc  = (const float*)d_in[8];
    const float* bfc  = (const float*)d_in[9];
    float* out = (float*)d_out;

    float *G0, *G1, *H1, *HT;
    cudaGetSymbolAddress((void**)&G0, g_G0);
    cudaGetSymbolAddress((void**)&G1, g_G1);
    cudaGetSymbolAddress((void**)&H1, g_H1);
    cudaGetSymbolAddress((void**)&HT, g_HT);

    cudaFuncSetAttribute(lstm_kernel, cudaFuncAttributeMaxDynamicSharedMemorySize,
                         LSTM_SMEM_BYTES);

    dim3 gemm_grid(1024 / 128, MROWS / 128);   // 8 n-tiles x 1024 m-tiles

    // layer 0: input gates (tensor cores), then bidirectional recurrence -> H1
    gate_gemm_tc<DIN><<<gemm_grid, 256>>>(X, Wih0, b0, lens, G0);
    lstm_kernel<<<128, 512, LSTM_SMEM_BYTES>>>(G0, Whh0, lens, H1, nullptr, 1);

    // layer 1: input gates over H1 (tensor cores), recurrence -> final hiddens
    gate_gemm_tc<2 * HID><<<gemm_grid, 256>>>(H1, Wih1, b1, lens, G1);
    lstm_kernel<<<128, 512, LSTM_SMEM_BYTES>>>(G1, Whh1, lens, nullptr, HT, 0);

    // classifier head
    fc_kernel<<<BATCH, 32>>>(HT, Wfc, bfc, out);
}

// round 6
// speedup vs baseline: 1.6615x; 1.0987x over previous
#include <cuda_runtime.h>
#include <math.h>

// ---------------------------------------------------------------------------
// Problem constants
// ---------------------------------------------------------------------------
#define BATCH 256
#define TLEN  512
#define DIN   64
#define HID   128
#define G4    512              // 4*H
#define NCLS  12
#define MROWS (BATCH * TLEN)   // 131072

typedef unsigned long long ull;

// ---- packed f32x2 helpers ----
__device__ __forceinline__ ull pack2(float lo, float hi) {
    ull r; asm("mov.b64 %0, {%1, %2};" : "=l"(r) : "f"(lo), "f"(hi)); return r;
}
__device__ __forceinline__ void unpack2(ull v, float& lo, float& hi) {
    asm("mov.b64 {%0, %1}, %2;" : "=f"(lo), "=f"(hi) : "l"(v));
}
__device__ __forceinline__ ull ffma2(ull a, ull b, ull c) {
    ull d; asm("fma.rn.f32x2 %0, %1, %2, %3;" : "=l"(d) : "l"(a), "l"(b), "l"(c));
    return d;
}
__device__ __forceinline__ float hsum2(ull v) {
    float lo, hi; unpack2(v, lo, hi); return lo + hi;
}

// ---- tf32 mma helpers ----
__device__ __forceinline__ unsigned cvt_tf32(float x) {
    unsigned u; asm("cvt.rna.tf32.f32 %0, %1;" : "=r"(u) : "f"(x)); return u;
}
__device__ __forceinline__ void mma_tf32(float d[4], const unsigned a[4],
                                         unsigned b0, unsigned b1) {
    asm("mma.sync.aligned.m16n8k8.row.col.f32.tf32.tf32.f32 "
        "{%0,%1,%2,%3},{%4,%5,%6,%7},{%8,%9},{%0,%1,%2,%3};"
        : "+f"(d[0]), "+f"(d[1]), "+f"(d[2]), "+f"(d[3])
        : "r"(a[0]), "r"(a[1]), "r"(a[2]), "r"(a[3]), "r"(b0), "r"(b1));
}

// ---------------------------------------------------------------------------
// Scratch (device globals; allocation in kernel_launch is forbidden)
// ---------------------------------------------------------------------------
__device__ float g_G0[(size_t)2 * BATCH * TLEN * G4];   // layer0 gate pre-acts [dir][b][t][g]
__device__ float g_G1[(size_t)2 * BATCH * TLEN * G4];   // layer1 gate pre-acts
__device__ float g_H1[(size_t)BATCH * TLEN * 2 * HID];  // layer0 output [b][t][256]
__device__ float g_HT[(size_t)2 * BATCH * HID];         // layer1 final hidden [dir][b][128]

// ---------------------------------------------------------------------------
// Gate-input GEMM on tensor cores (tf32 mma.sync m16n8k8, "NT" layout).
//   Unchanged from R4 (proven): CTA tile 128x128, BK=32, 8 warps.
// ---------------------------------------------------------------------------
template <int KDIM>
__global__ __launch_bounds__(256, 2)
void gate_gemm_tc(const float* __restrict__ A,
                  const float* __restrict__ W,
                  const float* __restrict__ bias,
                  const int*   __restrict__ lens,
                  float*       __restrict__ G)
{
    constexpr int BM = 128, BN = 128, BK = 32, LDSA = BK + 4;   // 36
    __shared__ unsigned As[BM * LDSA];
    __shared__ unsigned Ws[BN * LDSA];

    const int m0 = blockIdx.y * BM;
    const int n0 = blockIdx.x * BN;
    const int b  = m0 >> 9;
    if ((m0 & 511) >= lens[b]) return;

    const int tid  = threadIdx.x;
    const int lane = tid & 31;
    const int w    = tid >> 5;
    const int g    = lane >> 2;
    const int t    = lane & 3;
    const int wm   = w >> 1;
    const int wn   = w & 1;

    const int lrow = tid >> 1;
    const int lcol = (tid & 1) * 16;

    float d[2][8][4];
#pragma unroll
    for (int mi = 0; mi < 2; mi++)
#pragma unroll
        for (int ni = 0; ni < 8; ni++)
#pragma unroll
            for (int c = 0; c < 4; c++) d[mi][ni][c] = 0.f;

    for (int k0 = 0; k0 < KDIM; k0 += BK) {
        float4 av[4], wv[4];
        const float* Ap = A + (size_t)(m0 + lrow) * KDIM + k0 + lcol;
        const float* Wp = W + (size_t)(n0 + lrow) * KDIM + k0 + lcol;
#pragma unroll
        for (int i = 0; i < 4; i++) {
            av[i] = *(const float4*)(Ap + 4 * i);
            wv[i] = *(const float4*)(Wp + 4 * i);
        }
        __syncthreads();
#pragma unroll
        for (int i = 0; i < 4; i++) {
            uint4 ua = { cvt_tf32(av[i].x), cvt_tf32(av[i].y),
                         cvt_tf32(av[i].z), cvt_tf32(av[i].w) };
            uint4 uw = { cvt_tf32(wv[i].x), cvt_tf32(wv[i].y),
                         cvt_tf32(wv[i].z), cvt_tf32(wv[i].w) };
            *(uint4*)&As[lrow * LDSA + lcol + 4 * i] = ua;
            *(uint4*)&Ws[lrow * LDSA + lcol + 4 * i] = uw;
        }
        __syncthreads();

#pragma unroll
        for (int kk = 0; kk < BK; kk += 8) {
            unsigned a[2][4];
#pragma unroll
            for (int mi = 0; mi < 2; mi++) {
                const int r = wm * 32 + mi * 16;
                a[mi][0] = As[(r + g)     * LDSA + kk + t];
                a[mi][1] = As[(r + g + 8) * LDSA + kk + t];
                a[mi][2] = As[(r + g)     * LDSA + kk + t + 4];
                a[mi][3] = As[(r + g + 8) * LDSA + kk + t + 4];
            }
#pragma unroll
            for (int ni = 0; ni < 8; ni++) {
                const int c = wn * 64 + ni * 8;
                const unsigned b0 = Ws[(c + g) * LDSA + kk + t];
                const unsigned b1 = Ws[(c + g) * LDSA + kk + t + 4];
                mma_tf32(d[0][ni], a[0], b0, b1);
                mma_tf32(d[1][ni], a[1], b0, b1);
            }
        }
    }

#pragma unroll
    for (int ni = 0; ni < 8; ni++) {
        const int col  = n0 + wn * 64 + ni * 8 + 2 * t;
        const int dirn = col >> 9;
        const int gg   = col & 511;
        const float2 bv = *(const float2*)(bias + col);
#pragma unroll
        for (int mi = 0; mi < 2; mi++) {
            const int m  = m0 + wm * 32 + mi * 16 + g;
            const int tt = m & 511;
            const size_t base = ((((size_t)dirn * BATCH + b) * TLEN) + tt) * G4 + gg;
            float2 v0 = { d[mi][ni][0] + bv.x, d[mi][ni][1] + bv.y };
            float2 v1 = { d[mi][ni][2] + bv.x, d[mi][ni][3] + bv.y };
            *(float2*)&G[base]                  = v0;   // row m
            *(float2*)&G[base + 8 * (size_t)G4] = v1;   // row m+8
        }
    }
}

// ---------------------------------------------------------------------------
// Persistent LSTM recurrence (fp32, exact), slice-parallel form.
//   One CTA per (dir, 4-batch group) -> 128 CTAs, one wave, 512 threads.
//   Thread (q = 8*warp + lane&7, s = lane>>3) owns the 4 gate rows of hidden
//   unit q over j-slice [32s, 32s+32) for all 4 batches.  Per-step:
//     - dot partials (FFMA2; W: 8 j in regs + 24 j in smem; h: 1-wf loads)
//     - shfl.bfly over the 4 slice-lanes -> full gate pre-acts
//     - lane s does the pointwise for batch s entirely in registers
//     - h written to a double-buffered smem block; ONE barrier per step.
// ---------------------------------------------------------------------------
#define WROW   100                              // 96 smem j + 4 pad
#define HBUF   576                              // 4 batches * (4 slices * 36)
#define LSTM_SMEM_BYTES ((G4 * WROW + 2 * HBUF) * 4)   // 209408

__device__ __forceinline__ float sigm(float x) { return 1.f / (1.f + expf(-x)); }

__global__ __launch_bounds__(512)
void lstm_kernel(const float* __restrict__ G,
                 const float* __restrict__ Whh,   // [2][512][128]
                 const int*   __restrict__ lens,
                 float*       __restrict__ h1,    // may be null
                 float*       __restrict__ hT,    // may be null
                 int write_seq)
{
    extern __shared__ float sm[];
    float* Wsm  = sm;                     // 512 * 100
    float* hbuf = sm + G4 * WROW;         // 2 * 576

    const int tid  = threadIdx.x;
    const int lane = tid & 31;
    const int w    = tid >> 5;
    const int l7   = lane & 7;
    const int s    = lane >> 3;           // j-slice == batch slot
    const int q    = (w << 3) | l7;       // hidden unit 0..127

    const int dir = blockIdx.x >> 6;
    const int bb  = (blockIdx.x & 63) * 4;
    const int bm  = bb + s;               // this thread's batch

    const float* Wd = Whh + (size_t)dir * G4 * HID;

    // ---- fill Wsm: this thread's 4 rows, j = 32s+8 .. 32s+31 ----
#pragma unroll
    for (int i = 0; i < 4; i++) {
        const int row = i * 128 + q;
        const float* src = Wd + (size_t)row * HID + 32 * s + 8;
        float* dst = Wsm + row * WROW + s * 24;
#pragma unroll
        for (int p = 0; p < 6; p++)
            *(float4*)(dst + 4 * p) = *(const float4*)(src + 4 * p);
    }
    // ---- W regs: j = 32s .. 32s+7 for the 4 rows ----
    ull wr[16];
#pragma unroll
    for (int i = 0; i < 4; i++) {
        const float4* p = (const float4*)(Wd + (size_t)(i * 128 + q) * HID + 32 * s);
        float4 f0 = p[0], f1 = p[1];
        wr[i * 4 + 0] = pack2(f0.x, f0.y);
        wr[i * 4 + 1] = pack2(f0.z, f0.w);
        wr[i * 4 + 2] = pack2(f1.x, f1.y);
        wr[i * 4 + 3] = pack2(f1.z, f1.w);
    }

    const int hslot = s * 144 + (q >> 5) * 36 + (q & 31);
    hbuf[hslot] = 0.f;                    // zero buffer 0 (all 512 slots covered)

    const int l0 = lens[bb], l1 = lens[bb + 1], l2 = lens[bb + 2], l3 = lens[bb + 3];
    const int Tmax  = max(max(l0, l1), max(l2, l3));
    const int mylen = (s == 0) ? l0 : (s == 1) ? l1 : (s == 2) ? l2 : l3;

    const float* Gb = G + (((size_t)dir * BATCH + bm) << 18);   // [t][512]

    float h_cur = 0.f, c_cur = 0.f;

    __syncthreads();

    // prefetch gate inputs for step 0 (4 gates of unit q, batch bm)
    float gv[4];
    {
        const int t = dir ? (mylen - 1) : 0;
#pragma unroll
        for (int i = 0; i < 4; i++) gv[i] = Gb[(size_t)t * G4 + i * 128 + q];
    }

    int cur = 0;
    for (int step = 0; step < Tmax; step++) {
        // prefetch next step's gate inputs (hidden behind the dot work)
        float gvn[4];
        {
            const int sn = (step + 1 < Tmax) ? step + 1 : step;
            int t = dir ? (mylen - 1 - sn) : sn;
            t = t < 0 ? 0 : t;
#pragma unroll
            for (int i = 0; i < 4; i++) gvn[i] = Gb[(size_t)t * G4 + i * 128 + q];
        }

        const float* hc = hbuf + cur * HBUF;
        ull acc[16];
#pragma unroll
        for (int k = 0; k < 16; k++) acc[k] = 0ull;

        // reg-j part: j-local 0..7
#pragma unroll
        for (int p = 0; p < 2; p++) {
            ulonglong2 hv[4];
#pragma unroll
            for (int b = 0; b < 4; b++)
                hv[b] = *(const ulonglong2*)(hc + b * 144 + s * 36 + 4 * p);
#pragma unroll
            for (int i = 0; i < 4; i++) {
                const ull w0 = wr[i * 4 + 2 * p], w1 = wr[i * 4 + 2 * p + 1];
#pragma unroll
                for (int b = 0; b < 4; b++) {
                    acc[i * 4 + b] = ffma2(w0, hv[b].x, acc[i * 4 + b]);
                    acc[i * 4 + b] = ffma2(w1, hv[b].y, acc[i * 4 + b]);
                }
            }
        }
        // smem-j part: j-local 8..31
#pragma unroll
        for (int p = 0; p < 6; p++) {
            ulonglong2 hv[4];
#pragma unroll
            for (int b = 0; b < 4; b++)
                hv[b] = *(const ulonglong2*)(hc + b * 144 + s * 36 + 8 + 4 * p);
#pragma unroll
            for (int i = 0; i < 4; i++) {
                const ulonglong2 wv =
                    *(const ulonglong2*)(Wsm + (i * 128 + q) * WROW + s * 24 + 4 * p);
#pragma unroll
                for (int b = 0; b < 4; b++) {
                    acc[i * 4 + b] = ffma2(wv.x, hv[b].x, acc[i * 4 + b]);
                    acc[i * 4 + b] = ffma2(wv.y, hv[b].y, acc[i * 4 + b]);
                }
            }
        }

        // reduce packed halves, then across the 4 slice-lanes (same warp)
        float gate[16];
#pragma unroll
        for (int k = 0; k < 16; k++) gate[k] = hsum2(acc[k]);
#pragma unroll
        for (int k = 0; k < 16; k++)
            gate[k] += __shfl_xor_sync(0xffffffffu, gate[k], 8);
#pragma unroll
        for (int k = 0; k < 16; k++)
            gate[k] += __shfl_xor_sync(0xffffffffu, gate[k], 16);

        // pointwise: lane s handles batch s for unit q, all in registers
        if (step < mylen) {
            const float pi = gate[0 * 4 + s] + gv[0];
            const float pf = gate[1 * 4 + s] + gv[1];
            const float pg = gate[2 * 4 + s] + gv[2];
            const float po = gate[3 * 4 + s] + gv[3];
            c_cur = fmaf(sigm(pf), c_cur, sigm(pi) * tanhf(pg));
            h_cur = sigm(po) * tanhf(c_cur);
            if (write_seq) {
                const int t = dir ? (mylen - 1 - step) : step;
                h1[((size_t)bm * TLEN + t) * (2 * HID) + dir * HID + q] = h_cur;
            }
        }
        hbuf[(cur ^ 1) * HBUF + hslot] = h_cur;   // publish (frozen value if done)
        __syncthreads();
        cur ^= 1;
        gv[0] = gvn[0]; gv[1] = gvn[1]; gv[2] = gvn[2]; gv[3] = gvn[3];
    }

    if (hT)
        hT[((size_t)dir * BATCH + bm) * HID + q] = h_cur;

    if (write_seq) {
        // zero-fill padded region (reference masks hs to zero at t >= len)
        const int lq4[4] = {l0, l1, l2, l3};
#pragma unroll
        for (int qq = 0; qq < 4; qq++) {
            const int b  = bb + qq;
            const int lq = lq4[qq];
            const int ntail = (TLEN - lq) * HID;
            for (int idx = tid; idx < ntail; idx += 512) {
                const int t = lq + (idx >> 7);
                const int k = idx & 127;
                h1[((size_t)b * TLEN + t) * (2 * HID) + dir * HID + k] = 0.f;
            }
        }
    }
}

// ---------------------------------------------------------------------------
// FC + log_softmax.  h = concat([hT_backward, hT_forward]).
// ---------------------------------------------------------------------------
__global__ __launch_bounds__(32)
void fc_kernel(const float* __restrict__ HT,    // [2][256][128] (dir0=fwd, dir1=bwd)
               const float* __restrict__ Wfc,   // [12][256]
               const float* __restrict__ bfc,   // [12]
               float*       __restrict__ out)   // [256][12]
{
    const int b = blockIdx.x;
    const int c = threadIdx.x;
    float acc = 0.f;
    if (c < NCLS) {
        acc = bfc[c];
        const float* hb = HT + ((size_t)BATCH + b) * HID;  // backward (first half)
        const float* hf = HT + (size_t)b * HID;            // forward  (second half)
        const float* w  = Wfc + c * (2 * HID);
#pragma unroll 4
        for (int k = 0; k < HID; k++) acc = fmaf(w[k], hb[k], acc);
#pragma unroll 4
        for (int k = 0; k < HID; k++) acc = fmaf(w[HID + k], hf[k], acc);
    }
    float mx = (c < NCLS) ? acc : -3.4e38f;
#pragma unroll
    for (int o = 16; o; o >>= 1) mx = fmaxf(mx, __shfl_xor_sync(0xffffffffu, mx, o));
    float e = (c < NCLS) ? expf(acc - mx) : 0.f;
    float ssum = e;
#pragma unroll
    for (int o = 16; o; o >>= 1) ssum += __shfl_xor_sync(0xffffffffu, ssum, o);
    if (c < NCLS) out[b * NCLS + c] = acc - mx - logf(ssum);
}

// ---------------------------------------------------------------------------
// Launch
// ---------------------------------------------------------------------------
extern "C" void kernel_launch(void* const* d_in, const int* in_sizes, int n_in,
                              void* d_out, int out_size)
{
    const float* X    = (const float*)d_in[0];
    const int*   lens = (const int*)  d_in[1];
    const float* Wih0 = (const float*)d_in[2];
    const float* Whh0 = (const float*)d_in[3];
    const float* b0   = (const float*)d_in[4];
    const float* Wih1 = (const float*)d_in[5];
    const float* Whh1 = (const float*)d_in[6];
    const float* b1   = (const float*)d_in[7];
    const float* Wfc  = (const float*)d_in[8];
    const float* bfc  = (const float*)d_in[9];
    float* out = (float*)d_out;

    float *G0, *G1, *H1, *HT;
    cudaGetSymbolAddress((void**)&G0, g_G0);
    cudaGetSymbolAddress((void**)&G1, g_G1);
    cudaGetSymbolAddress((void**)&H1, g_H1);
    cudaGetSymbolAddress((void**)&HT, g_HT);

    cudaFuncSetAttribute(lstm_kernel, cudaFuncAttributeMaxDynamicSharedMemorySize,
                         LSTM_SMEM_BYTES);

    dim3 gemm_grid(1024 / 128, MROWS / 128);   // 8 n-tiles x 1024 m-tiles

    // layer 0: input gates (tensor cores), then bidirectional recurrence -> H1
    gate_gemm_tc<DIN><<<gemm_grid, 256>>>(X, Wih0, b0, lens, G0);
    lstm_kernel<<<128, 512, LSTM_SMEM_BYTES>>>(G0, Whh0, lens, H1, nullptr, 1);

    // layer 1: input gates over H1 (tensor cores), recurrence -> final hiddens
    gate_gemm_tc<2 * HID><<<gemm_grid, 256>>>(H1, Wih1, b1, lens, G1);
    lstm_kernel<<<128, 512, LSTM_SMEM_BYTES>>>(G1, Whh1, lens, nullptr, HT, 0);

    // classifier head
    fc_kernel<<<BATCH, 32>>>(HT, Wfc, bfc, out);
}

// round 7
// speedup vs baseline: 2.4023x; 1.4458x over previous
#include <cuda_runtime.h>
#include <cuda_bf16.h>
#include <math.h>

// ---------------------------------------------------------------------------
// Problem constants
// ---------------------------------------------------------------------------
#define BATCH 256
#define TLEN  512
#define DIN   64
#define HID   128
#define G4    512              // 4*H
#define NCLS  12
#define MROWS (BATCH * TLEN)   // 131072

// ---- helpers ----
__device__ __forceinline__ unsigned cvt_tf32(float x) {
    unsigned u; asm("cvt.rna.tf32.f32 %0, %1;" : "=r"(u) : "f"(x)); return u;
}
__device__ __forceinline__ void mma_tf32(float d[4], const unsigned a[4],
                                         unsigned b0, unsigned b1) {
    asm("mma.sync.aligned.m16n8k8.row.col.f32.tf32.tf32.f32 "
        "{%0,%1,%2,%3},{%4,%5,%6,%7},{%8,%9},{%0,%1,%2,%3};"
        : "+f"(d[0]), "+f"(d[1]), "+f"(d[2]), "+f"(d[3])
        : "r"(a[0]), "r"(a[1]), "r"(a[2]), "r"(a[3]), "r"(b0), "r"(b1));
}
// pack two f32 -> bf16x2 (low = first arg)
__device__ __forceinline__ unsigned pack_bf16(float lo, float hi) {
    unsigned r;
    asm("cvt.rn.bf16x2.f32 %0, %1, %2;" : "=r"(r) : "f"(hi), "f"(lo));
    return r;
}
__device__ __forceinline__ void mma_bf16(float d[4], const unsigned a[4],
                                         unsigned b0, unsigned b1) {
    asm("mma.sync.aligned.m16n8k16.row.col.f32.bf16.bf16.f32 "
        "{%0,%1,%2,%3},{%4,%5,%6,%7},{%8,%9},{%0,%1,%2,%3};"
        : "+f"(d[0]), "+f"(d[1]), "+f"(d[2]), "+f"(d[3])
        : "r"(a[0]), "r"(a[1]), "r"(a[2]), "r"(a[3]), "r"(b0), "r"(b1));
}
__device__ __forceinline__ float tanh_fast(float x) {
    float y; asm("tanh.approx.f32 %0, %1;" : "=f"(y) : "f"(x)); return y;
}
__device__ __forceinline__ float sigm_fast(float x) {
    return fmaf(0.5f, tanh_fast(0.5f * x), 0.5f);
}

// ---------------------------------------------------------------------------
// Scratch (device globals; allocation in kernel_launch is forbidden)
// ---------------------------------------------------------------------------
__device__ float g_G0[(size_t)2 * BATCH * TLEN * G4];   // layer0 gate pre-acts [dir][b][t][g]
__device__ float g_G1[(size_t)2 * BATCH * TLEN * G4];   // layer1 gate pre-acts
__device__ float g_H1[(size_t)BATCH * TLEN * 2 * HID];  // layer0 output [b][t][256]
__device__ float g_HT[(size_t)2 * BATCH * HID];         // layer1 final hidden [dir][b][128]

// ---------------------------------------------------------------------------
// Gate-input GEMM on tensor cores (tf32 mma.sync m16n8k8, "NT" layout).
//   Proven from R4: CTA tile 128x128, BK=32, 8 warps.
// ---------------------------------------------------------------------------
template <int KDIM>
__global__ __launch_bounds__(256, 2)
void gate_gemm_tc(const float* __restrict__ A,
                  const float* __restrict__ W,
                  const float* __restrict__ bias,
                  const int*   __restrict__ lens,
                  float*       __restrict__ G)
{
    constexpr int BM = 128, BN = 128, BK = 32, LDSA = BK + 4;   // 36
    __shared__ unsigned As[BM * LDSA];
    __shared__ unsigned Ws[BN * LDSA];

    const int m0 = blockIdx.y * BM;
    const int n0 = blockIdx.x * BN;
    const int b  = m0 >> 9;
    if ((m0 & 511) >= lens[b]) return;

    const int tid  = threadIdx.x;
    const int lane = tid & 31;
    const int w    = tid >> 5;
    const int g    = lane >> 2;
    const int t    = lane & 3;
    const int wm   = w >> 1;
    const int wn   = w & 1;

    const int lrow = tid >> 1;
    const int lcol = (tid & 1) * 16;

    float d[2][8][4];
#pragma unroll
    for (int mi = 0; mi < 2; mi++)
#pragma unroll
        for (int ni = 0; ni < 8; ni++)
#pragma unroll
            for (int c = 0; c < 4; c++) d[mi][ni][c] = 0.f;

    for (int k0 = 0; k0 < KDIM; k0 += BK) {
        float4 av[4], wv[4];
        const float* Ap = A + (size_t)(m0 + lrow) * KDIM + k0 + lcol;
        const float* Wp = W + (size_t)(n0 + lrow) * KDIM + k0 + lcol;
#pragma unroll
        for (int i = 0; i < 4; i++) {
            av[i] = *(const float4*)(Ap + 4 * i);
            wv[i] = *(const float4*)(Wp + 4 * i);
        }
        __syncthreads();
#pragma unroll
        for (int i = 0; i < 4; i++) {
            uint4 ua = { cvt_tf32(av[i].x), cvt_tf32(av[i].y),
                         cvt_tf32(av[i].z), cvt_tf32(av[i].w) };
            uint4 uw = { cvt_tf32(wv[i].x), cvt_tf32(wv[i].y),
                         cvt_tf32(wv[i].z), cvt_tf32(wv[i].w) };
            *(uint4*)&As[lrow * LDSA + lcol + 4 * i] = ua;
            *(uint4*)&Ws[lrow * LDSA + lcol + 4 * i] = uw;
        }
        __syncthreads();

#pragma unroll
        for (int kk = 0; kk < BK; kk += 8) {
            unsigned a[2][4];
#pragma unroll
            for (int mi = 0; mi < 2; mi++) {
                const int r = wm * 32 + mi * 16;
                a[mi][0] = As[(r + g)     * LDSA + kk + t];
                a[mi][1] = As[(r + g + 8) * LDSA + kk + t];
                a[mi][2] = As[(r + g)     * LDSA + kk + t + 4];
                a[mi][3] = As[(r + g + 8) * LDSA + kk + t + 4];
            }
#pragma unroll
            for (int ni = 0; ni < 8; ni++) {
                const int c = wn * 64 + ni * 8;
                const unsigned b0 = Ws[(c + g) * LDSA + kk + t];
                const unsigned b1 = Ws[(c + g) * LDSA + kk + t + 4];
                mma_tf32(d[0][ni], a[0], b0, b1);
                mma_tf32(d[1][ni], a[1], b0, b1);
            }
        }
    }

#pragma unroll
    for (int ni = 0; ni < 8; ni++) {
        const int col  = n0 + wn * 64 + ni * 8 + 2 * t;
        const int dirn = col >> 9;
        const int gg   = col & 511;
        const float2 bv = *(const float2*)(bias + col);
#pragma unroll
        for (int mi = 0; mi < 2; mi++) {
            const int m  = m0 + wm * 32 + mi * 16 + g;
            const int tt = m & 511;
            const size_t base = ((((size_t)dirn * BATCH + b) * TLEN) + tt) * G4 + gg;
            float2 v0 = { d[mi][ni][0] + bv.x, d[mi][ni][1] + bv.y };
            float2 v1 = { d[mi][ni][2] + bv.x, d[mi][ni][3] + bv.y };
            *(float2*)&G[base]                  = v0;   // row m
            *(float2*)&G[base + 8 * (size_t)G4] = v1;   // row m+8
        }
    }
}

// ---------------------------------------------------------------------------
// Tensor-core LSTM recurrence.
//   One CTA = (dir, 16 batches) -> 32 CTAs, 512 threads = 16 warps.
//   Per step: D[16 batches x 512 gates] = h_bf16[16x128] @ Whh_bf16^T via
//   mma.sync m16n8k16 bf16 (fp32 accum).  Warp w owns hidden units
//   [8w, 8w+8) x 4 gate types (i,f,g,o) as its 4 n-tiles, so the full
//   pointwise for a cell is register-local to one lane (2 units x 2 batches).
//   W fragments: k-steps 0-3 in regs (32 regs), 4-7 in smem (64 KB).
//   h published in A-fragment order (bf16x2); double-buffered; 1 barrier/step.
//   Cell state c stays exact fp32 in registers.
// ---------------------------------------------------------------------------
#define LSTM_TC_SMEM ((16384 + 2048) * 4)     // wfrag 64 KB + hfrag 2x4 KB

__global__ __launch_bounds__(512, 1)
void lstm_tc_kernel(const float* __restrict__ G,
                    const float* __restrict__ Whh,   // [2][512][128] fp32
                    const int*   __restrict__ lens,
                    float*       __restrict__ h1,    // may be null
                    float*       __restrict__ hT,    // may be null
                    int write_seq)
{
    extern __shared__ unsigned usm[];
    unsigned* wfrag = usm;            // [w][ks-4][gt][lane] x uint2 : 16384 u32
    unsigned* hfrag = usm + 16384;    // 2 buffers x [ks][lane][4]   : 2048 u32

    const int tid  = threadIdx.x;
    const int lane = tid & 31;
    const int w    = tid >> 5;        // warp 0..15 -> units [8w, 8w+8)
    const int g    = lane >> 2;       // groupID
    const int t    = lane & 3;        // threadID in group
    const int q0   = 8 * w + 2 * t;   // this lane's first unit

    const int dir = blockIdx.x >> 4;
    const int bb  = (blockIdx.x & 15) * 16;

    const float* Wd = Whh + (size_t)dir * G4 * HID;

    // ---- build W fragments (B-frag layout: b0 = W[row][16ks+2t, +1]) ----
    unsigned wreg[32];
#pragma unroll
    for (int ks = 0; ks < 8; ks++) {
#pragma unroll
        for (int gt = 0; gt < 4; gt++) {
            const float* row = Wd + (size_t)(gt * 128 + 8 * w + g) * HID + 16 * ks + 2 * t;
            float2 lo = *(const float2*)row;
            float2 hi = *(const float2*)(row + 8);
            unsigned b0 = pack_bf16(lo.x, lo.y);
            unsigned b1 = pack_bf16(hi.x, hi.y);
            if (ks < 4) {
                wreg[(ks * 4 + gt) * 2]     = b0;
                wreg[(ks * 4 + gt) * 2 + 1] = b1;
            } else {
                const unsigned idx = (((w * 4 + (ks - 4)) * 4 + gt) * 32 + lane) * 2;
                wfrag[idx]     = b0;
                wfrag[idx + 1] = b1;
            }
        }
    }

    // zero h-fragment buffer 0
    hfrag[tid]       = 0u;
    hfrag[tid + 512] = 0u;

    const int len0 = lens[bb + g];        // batch m = g
    const int len1 = lens[bb + g + 8];    // batch m = g+8
    int Tmax = 0;
#pragma unroll
    for (int i = 0; i < 16; i++) Tmax = max(Tmax, lens[bb + i]);

    const size_t gbase0 = ((size_t)(dir * BATCH + bb + g))     << 18;   // *T*G4
    const size_t gbase1 = ((size_t)(dir * BATCH + bb + g + 8)) << 18;

    float c00 = 0.f, c01 = 0.f, c10 = 0.f, c11 = 0.f;   // cell state (2b x 2u)
    float h00 = 0.f, h01 = 0.f, h10 = 0.f, h11 = 0.f;

    // h-frag publish slot (lane' == lane; reg pair depends on w parity)
    const int regA = (w & 1) ? 2 : 0;
    const int ksp  = w >> 1;

    __syncthreads();

    int cur = 0;
    for (int s = 0; s < Tmax; s++) {
        // ---- gate-input loads (consumed ~after the mma block) ----
        int t0 = dir ? (len0 - 1 - s) : s; t0 = t0 < 0 ? 0 : t0;
        int t1 = dir ? (len1 - 1 - s) : s; t1 = t1 < 0 ? 0 : t1;
        float2 gva[4], gvb[4];
#pragma unroll
        for (int gt = 0; gt < 4; gt++) {
            gva[gt] = *(const float2*)(G + gbase0 + (size_t)t0 * G4 + gt * 128 + q0);
            gvb[gt] = *(const float2*)(G + gbase1 + (size_t)t1 * G4 + gt * 128 + q0);
        }

        // ---- mma: D[16 x 32-own-gates] over K=128 ----
        float acc[4][4];
#pragma unroll
        for (int gt = 0; gt < 4; gt++)
#pragma unroll
            for (int c = 0; c < 4; c++) acc[gt][c] = 0.f;

        const unsigned hbase = cur * 1024;
#pragma unroll
        for (int ks = 0; ks < 8; ks++) {
            uint4 av = *(const uint4*)&hfrag[hbase + ks * 128 + lane * 4];
            unsigned a[4] = { av.x, av.y, av.z, av.w };
            if (ks < 4) {
#pragma unroll
                for (int gt = 0; gt < 4; gt++)
                    mma_bf16(acc[gt], a, wreg[(ks * 4 + gt) * 2],
                                         wreg[(ks * 4 + gt) * 2 + 1]);
            } else {
#pragma unroll
                for (int gt = 0; gt < 4; gt++) {
                    uint2 bfr = *(const uint2*)
                        &wfrag[(((w * 4 + (ks - 4)) * 4 + gt) * 32 + lane) * 2];
                    mma_bf16(acc[gt], a, bfr.x, bfr.y);
                }
            }
        }

        // ---- pointwise, batch m=g (acc cols 0,1) ----
        if (s < len0) {
            const float pi0 = acc[0][0] + gva[0].x, pi1 = acc[0][1] + gva[0].y;
            const float pf0 = acc[1][0] + gva[1].x, pf1 = acc[1][1] + gva[1].y;
            const float pg0 = acc[2][0] + gva[2].x, pg1 = acc[2][1] + gva[2].y;
            const float po0 = acc[3][0] + gva[3].x, po1 = acc[3][1] + gva[3].y;
            c00 = fmaf(sigm_fast(pf0), c00, sigm_fast(pi0) * tanh_fast(pg0));
            c01 = fmaf(sigm_fast(pf1), c01, sigm_fast(pi1) * tanh_fast(pg1));
            h00 = sigm_fast(po0) * tanh_fast(c00);
            h01 = sigm_fast(po1) * tanh_fast(c01);
            if (write_seq) {
                const int tt = dir ? (len0 - 1 - s) : s;
                *(float2*)&h1[((size_t)(bb + g) * TLEN + tt) * (2 * HID) + dir * HID + q0]
                    = make_float2(h00, h01);
            }
        }
        // ---- pointwise, batch m=g+8 (acc cols 2,3) ----
        if (s < len1) {
            const float pi0 = acc[0][2] + gvb[0].x, pi1 = acc[0][3] + gvb[0].y;
            const float pf0 = acc[1][2] + gvb[1].x, pf1 = acc[1][3] + gvb[1].y;
            const float pg0 = acc[2][2] + gvb[2].x, pg1 = acc[2][3] + gvb[2].y;
            const float po0 = acc[3][2] + gvb[3].x, po1 = acc[3][3] + gvb[3].y;
            c10 = fmaf(sigm_fast(pf0), c10, sigm_fast(pi0) * tanh_fast(pg0));
            c11 = fmaf(sigm_fast(pf1), c11, sigm_fast(pi1) * tanh_fast(pg1));
            h10 = sigm_fast(po0) * tanh_fast(c10);
            h11 = sigm_fast(po1) * tanh_fast(c11);
            if (write_seq) {
                const int tt = dir ? (len1 - 1 - s) : s;
                *(float2*)&h1[((size_t)(bb + g + 8) * TLEN + tt) * (2 * HID) + dir * HID + q0]
                    = make_float2(h10, h11);
            }
        }

        // ---- publish h (bf16x2) into the other buffer, A-frag order ----
        const unsigned obase = (cur ^ 1) * 1024 + ksp * 128 + lane * 4;
        hfrag[obase + regA]     = pack_bf16(h00, h01);
        hfrag[obase + regA + 1] = pack_bf16(h10, h11);
        __syncthreads();
        cur ^= 1;
    }

    if (hT) {
        *(float2*)&hT[((size_t)(dir * BATCH + bb + g))     * HID + q0] = make_float2(h00, h01);
        *(float2*)&hT[((size_t)(dir * BATCH + bb + g + 8)) * HID + q0] = make_float2(h10, h11);
    }

    if (write_seq) {
        // zero-fill padded region (reference masks hs to zero at t >= len)
        for (int qq = 0; qq < 16; qq++) {
            const int b  = bb + qq;
            const int lq = lens[b];
            const int ntail = (TLEN - lq) * HID;
            for (int idx = tid; idx < ntail; idx += 512) {
                const int tt = lq + (idx >> 7);
                const int k  = idx & 127;
                h1[((size_t)b * TLEN + tt) * (2 * HID) + dir * HID + k] = 0.f;
            }
        }
    }
}

// ---------------------------------------------------------------------------
// FC + log_softmax.  h = concat([hT_backward, hT_forward]).
// ---------------------------------------------------------------------------
__global__ __launch_bounds__(32)
void fc_kernel(const float* __restrict__ HT,    // [2][256][128] (dir0=fwd, dir1=bwd)
               const float* __restrict__ Wfc,   // [12][256]
               const float* __restrict__ bfc,   // [12]
               float*       __restrict__ out)   // [256][12]
{
    const int b = blockIdx.x;
    const int c = threadIdx.x;
    float acc = 0.f;
    if (c < NCLS) {
        acc = bfc[c];
        const float* hb = HT + ((size_t)BATCH + b) * HID;  // backward (first half)
        const float* hf = HT + (size_t)b * HID;            // forward  (second half)
        const float* w  = Wfc + c * (2 * HID);
#pragma unroll 4
        for (int k = 0; k < HID; k++) acc = fmaf(w[k], hb[k], acc);
#pragma unroll 4
        for (int k = 0; k < HID; k++) acc = fmaf(w[HID + k], hf[k], acc);
    }
    float mx = (c < NCLS) ? acc : -3.4e38f;
#pragma unroll
    for (int o = 16; o; o >>= 1) mx = fmaxf(mx, __shfl_xor_sync(0xffffffffu, mx, o));
    float e = (c < NCLS) ? expf(acc - mx) : 0.f;
    float ssum = e;
#pragma unroll
    for (int o = 16; o; o >>= 1) ssum += __shfl_xor_sync(0xffffffffu, ssum, o);
    if (c < NCLS) out[b * NCLS + c] = acc - mx - logf(ssum);
}

// ---------------------------------------------------------------------------
// Launch
// ---------------------------------------------------------------------------
extern "C" void kernel_launch(void* const* d_in, const int* in_sizes, int n_in,
                              void* d_out, int out_size)
{
    const float* X    = (const float*)d_in[0];
    const int*   lens = (const int*)  d_in[1];
    const float* Wih0 = (const float*)d_in[2];
    const float* Whh0 = (const float*)d_in[3];
    const float* b0   = (const float*)d_in[4];
    const float* Wih1 = (const float*)d_in[5];
    const float* Whh1 = (const float*)d_in[6];
    const float* b1   = (const float*)d_in[7];
    const float* Wfc  = (const float*)d_in[8];
    const float* bfc  = (const float*)d_in[9];
    float* out = (float*)d_out;

    float *G0, *G1, *H1, *HT;
    cudaGetSymbolAddress((void**)&G0, g_G0);
    cudaGetSymbolAddress((void**)&G1, g_G1);
    cudaGetSymbolAddress((void**)&H1, g_H1);
    cudaGetSymbolAddress((void**)&HT, g_HT);

    cudaFuncSetAttribute(lstm_tc_kernel, cudaFuncAttributeMaxDynamicSharedMemorySize,
                         LSTM_TC_SMEM);

    dim3 gemm_grid(1024 / 128, MROWS / 128);   // 8 n-tiles x 1024 m-tiles

    // layer 0: input gates (tf32 TC), then bidirectional recurrence -> H1
    gate_gemm_tc<DIN><<<gemm_grid, 256>>>(X, Wih0, b0, lens, G0);
    lstm_tc_kernel<<<32, 512, LSTM_TC_SMEM>>>(G0, Whh0, lens, H1, nullptr, 1);

    // layer 1: input gates over H1 (tf32 TC), recurrence -> final hiddens
    gate_gemm_tc<2 * HID><<<gemm_grid, 256>>>(H1, Wih1, b1, lens, G1);
    lstm_tc_kernel<<<32, 512, LSTM_TC_SMEM>>>(G1, Whh1, lens, nullptr, HT, 0);

    // classifier head
    fc_kernel<<<BATCH, 32>>>(HT, Wfc, bfc, out);
}

// round 8
// speedup vs baseline: 3.1954x; 1.3302x over previous
#include <cuda_runtime.h>
#include <cuda_bf16.h>
#include <math.h>

// ---------------------------------------------------------------------------
// Problem constants
// ---------------------------------------------------------------------------
#define BATCH 256
#define TLEN  512
#define DIN   64
#define HID   128
#define G4    512              // 4*H
#define NCLS  12
#define MROWS (BATCH * TLEN)   // 131072

// ---- helpers ----
__device__ __forceinline__ unsigned cvt_tf32(float x) {
    unsigned u; asm("cvt.rna.tf32.f32 %0, %1;" : "=r"(u) : "f"(x)); return u;
}
__device__ __forceinline__ void mma_tf32(float d[4], const unsigned a[4],
                                         unsigned b0, unsigned b1) {
    asm("mma.sync.aligned.m16n8k8.row.col.f32.tf32.tf32.f32 "
        "{%0,%1,%2,%3},{%4,%5,%6,%7},{%8,%9},{%0,%1,%2,%3};"
        : "+f"(d[0]), "+f"(d[1]), "+f"(d[2]), "+f"(d[3])
        : "r"(a[0]), "r"(a[1]), "r"(a[2]), "r"(a[3]), "r"(b0), "r"(b1));
}
// pack two f32 -> bf16x2 (low = first arg)
__device__ __forceinline__ unsigned pack_bf16(float lo, float hi) {
    unsigned r;
    asm("cvt.rn.bf16x2.f32 %0, %1, %2;" : "=r"(r) : "f"(hi), "f"(lo));
    return r;
}
__device__ __forceinline__ void mma_bf16(float d[4], const unsigned a[4],
                                         unsigned b0, unsigned b1) {
    asm("mma.sync.aligned.m16n8k16.row.col.f32.bf16.bf16.f32 "
        "{%0,%1,%2,%3},{%4,%5,%6,%7},{%8,%9},{%0,%1,%2,%3};"
        : "+f"(d[0]), "+f"(d[1]), "+f"(d[2]), "+f"(d[3])
        : "r"(a[0]), "r"(a[1]), "r"(a[2]), "r"(a[3]), "r"(b0), "r"(b1));
}
__device__ __forceinline__ float tanh_fast(float x) {
    float y; asm("tanh.approx.f32 %0, %1;" : "=f"(y) : "f"(x)); return y;
}
__device__ __forceinline__ float sigm_fast(float x) {
    return fmaf(0.5f, tanh_fast(0.5f * x), 0.5f);
}

// ---------------------------------------------------------------------------
// Scratch (device globals; allocation in kernel_launch is forbidden)
// ---------------------------------------------------------------------------
__device__ float g_G0[(size_t)2 * BATCH * TLEN * G4];   // layer0 gate pre-acts [dir][b][t][g]
__device__ float g_G1[(size_t)2 * BATCH * TLEN * G4];   // layer1 gate pre-acts
__device__ float g_H1[(size_t)BATCH * TLEN * 2 * HID];  // layer0 output [b][t][256]
__device__ float g_HT[(size_t)2 * BATCH * HID];         // layer1 final hidden [dir][b][128]

// ---------------------------------------------------------------------------
// Gate-input GEMM on tensor cores (tf32 mma.sync m16n8k8, "NT" layout).
//   Proven from R4: CTA tile 128x128, BK=32, 8 warps.
// ---------------------------------------------------------------------------
template <int KDIM>
__global__ __launch_bounds__(256, 2)
void gate_gemm_tc(const float* __restrict__ A,
                  const float* __restrict__ W,
                  const float* __restrict__ bias,
                  const int*   __restrict__ lens,
                  float*       __restrict__ G)
{
    constexpr int BM = 128, BN = 128, BK = 32, LDSA = BK + 4;   // 36
    __shared__ unsigned As[BM * LDSA];
    __shared__ unsigned Ws[BN * LDSA];

    const int m0 = blockIdx.y * BM;
    const int n0 = blockIdx.x * BN;
    const int b  = m0 >> 9;
    if ((m0 & 511) >= lens[b]) return;

    const int tid  = threadIdx.x;
    const int lane = tid & 31;
    const int w    = tid >> 5;
    const int g    = lane >> 2;
    const int t    = lane & 3;
    const int wm   = w >> 1;
    const int wn   = w & 1;

    const int lrow = tid >> 1;
    const int lcol = (tid & 1) * 16;

    float d[2][8][4];
#pragma unroll
    for (int mi = 0; mi < 2; mi++)
#pragma unroll
        for (int ni = 0; ni < 8; ni++)
#pragma unroll
            for (int c = 0; c < 4; c++) d[mi][ni][c] = 0.f;

    for (int k0 = 0; k0 < KDIM; k0 += BK) {
        float4 av[4], wv[4];
        const float* Ap = A + (size_t)(m0 + lrow) * KDIM + k0 + lcol;
        const float* Wp = W + (size_t)(n0 + lrow) * KDIM + k0 + lcol;
#pragma unroll
        for (int i = 0; i < 4; i++) {
            av[i] = *(const float4*)(Ap + 4 * i);
            wv[i] = *(const float4*)(Wp + 4 * i);
        }
        __syncthreads();
#pragma unroll
        for (int i = 0; i < 4; i++) {
            uint4 ua = { cvt_tf32(av[i].x), cvt_tf32(av[i].y),
                         cvt_tf32(av[i].z), cvt_tf32(av[i].w) };
            uint4 uw = { cvt_tf32(wv[i].x), cvt_tf32(wv[i].y),
                         cvt_tf32(wv[i].z), cvt_tf32(wv[i].w) };
            *(uint4*)&As[lrow * LDSA + lcol + 4 * i] = ua;
            *(uint4*)&Ws[lrow * LDSA + lcol + 4 * i] = uw;
        }
        __syncthreads();

#pragma unroll
        for (int kk = 0; kk < BK; kk += 8) {
            unsigned a[2][4];
#pragma unroll
            for (int mi = 0; mi < 2; mi++) {
                const int r = wm * 32 + mi * 16;
                a[mi][0] = As[(r + g)     * LDSA + kk + t];
                a[mi][1] = As[(r + g + 8) * LDSA + kk + t];
                a[mi][2] = As[(r + g)     * LDSA + kk + t + 4];
                a[mi][3] = As[(r + g + 8) * LDSA + kk + t + 4];
            }
#pragma unroll
            for (int ni = 0; ni < 8; ni++) {
                const int c = wn * 64 + ni * 8;
                const unsigned b0 = Ws[(c + g) * LDSA + kk + t];
                const unsigned b1 = Ws[(c + g) * LDSA + kk + t + 4];
                mma_tf32(d[0][ni], a[0], b0, b1);
                mma_tf32(d[1][ni], a[1], b0, b1);
            }
        }
    }

#pragma unroll
    for (int ni = 0; ni < 8; ni++) {
        const int col  = n0 + wn * 64 + ni * 8 + 2 * t;
        const int dirn = col >> 9;
        const int gg   = col & 511;
        const float2 bv = *(const float2*)(bias + col);
#pragma unroll
        for (int mi = 0; mi < 2; mi++) {
            const int m  = m0 + wm * 32 + mi * 16 + g;
            const int tt = m & 511;
            const size_t base = ((((size_t)dirn * BATCH + b) * TLEN) + tt) * G4 + gg;
            float2 v0 = { d[mi][ni][0] + bv.x, d[mi][ni][1] + bv.y };
            float2 v1 = { d[mi][ni][2] + bv.x, d[mi][ni][3] + bv.y };
            *(float2*)&G[base]                  = v0;   // row m
            *(float2*)&G[base + 8 * (size_t)G4] = v1;   // row m+8
        }
    }
}

// ---------------------------------------------------------------------------
// Tensor-core LSTM recurrence (R7 structure + W-in-regs + gv prefetch).
//   One CTA = (dir, 16 batches) -> 32 CTAs, 512 threads = 16 warps.
//   Warp w owns units [8w,8w+8) x 4 gate types; pointwise register-local.
//   W fragments: k-steps 0-5 in regs (48 regs), 6-7 in smem (32 KB).
//   Gate inputs (gv) prefetched one step ahead via advancing pointers
//   (clamped by simply not advancing past len -> always in-bounds).
//   h published bf16x2 in A-fragment order, double-buffered, 1 barrier/step.
// ---------------------------------------------------------------------------
#define LSTM_TC_SMEM ((8192 + 2048) * 4)     // wfrag 32 KB + hfrag 2x4 KB

__global__ __launch_bounds__(512, 1)
void lstm_tc_kernel(const float* __restrict__ G,
                    const float* __restrict__ Whh,   // [2][512][128] fp32
                    const int*   __restrict__ lens,
                    float*       __restrict__ h1,    // may be null
                    float*       __restrict__ hT,    // may be null
                    int write_seq)
{
    extern __shared__ unsigned usm[];
    unsigned* wfrag = usm;            // [w][ks-6][gt][lane] x uint2 : 8192 u32
    unsigned* hfrag = usm + 8192;     // 2 buffers x [ks][lane][4]   : 2048 u32

    const int tid  = threadIdx.x;
    const int lane = tid & 31;
    const int w    = tid >> 5;        // warp 0..15 -> units [8w, 8w+8)
    const int g    = lane >> 2;       // groupID
    const int t    = lane & 3;        // threadID in group
    const int q0   = 8 * w + 2 * t;   // this lane's first unit

    const int dir = blockIdx.x >> 4;
    const int bb  = (blockIdx.x & 15) * 16;

    const float* Wd = Whh + (size_t)dir * G4 * HID;

    // ---- build W fragments (B-frag layout: b0 = W[row][16ks+2t, +1]) ----
    unsigned wreg[48];
#pragma unroll
    for (int ks = 0; ks < 8; ks++) {
#pragma unroll
        for (int gt = 0; gt < 4; gt++) {
            const float* row = Wd + (size_t)(gt * 128 + 8 * w + g) * HID + 16 * ks + 2 * t;
            float2 lo = *(const float2*)row;
            float2 hi = *(const float2*)(row + 8);
            unsigned b0 = pack_bf16(lo.x, lo.y);
            unsigned b1 = pack_bf16(hi.x, hi.y);
            if (ks < 6) {
                wreg[(ks * 4 + gt) * 2]     = b0;
                wreg[(ks * 4 + gt) * 2 + 1] = b1;
            } else {
                const unsigned idx = (((w * 2 + (ks - 6)) * 4 + gt) * 32 + lane) * 2;
                wfrag[idx]     = b0;
                wfrag[idx + 1] = b1;
            }
        }
    }

    // zero h-fragment buffer 0
    hfrag[tid]       = 0u;
    hfrag[tid + 512] = 0u;

    const int len0 = lens[bb + g];        // batch m = g
    const int len1 = lens[bb + g + 8];    // batch m = g+8
    int Tmax = 0;
#pragma unroll
    for (int i = 0; i < 16; i++) Tmax = max(Tmax, lens[bb + i]);

    // advancing gate-input pointers (start at t for step 0)
    const long long dstep = dir ? -(long long)G4 : (long long)G4;
    const float* p0 = G + (((size_t)(dir * BATCH + bb + g))     << 18)
                        + (size_t)(dir ? (len0 - 1) : 0) * G4;
    const float* p1 = G + (((size_t)(dir * BATCH + bb + g + 8)) << 18)
                        + (size_t)(dir ? (len1 - 1) : 0) * G4;

    float c00 = 0.f, c01 = 0.f, c10 = 0.f, c11 = 0.f;   // cell state (2b x 2u)
    float h00 = 0.f, h01 = 0.f, h10 = 0.f, h11 = 0.f;

    // h-frag publish slot
    const int regA = (w & 1) ? 2 : 0;
    const int ksp  = w >> 1;

    __syncthreads();

    // prefetch gate inputs for step 0
    float2 gva[4], gvb[4];
#pragma unroll
    for (int gt = 0; gt < 4; gt++) {
        gva[gt] = *(const float2*)(p0 + gt * 128 + q0);
        gvb[gt] = *(const float2*)(p1 + gt * 128 + q0);
    }

    int cur = 0;
    for (int s = 0; s < Tmax; s++) {
        // ---- advance pointers & prefetch step s+1 (hidden behind mma) ----
        if (s + 1 < len0) p0 += dstep;
        if (s + 1 < len1) p1 += dstep;
        float2 gna[4], gnb[4];
#pragma unroll
        for (int gt = 0; gt < 4; gt++) {
            gna[gt] = *(const float2*)(p0 + gt * 128 + q0);
            gnb[gt] = *(const float2*)(p1 + gt * 128 + q0);
        }

        // ---- mma: D[16 x own 32 gate-rows] over K=128 ----
        float acc[4][4];
#pragma unroll
        for (int gt = 0; gt < 4; gt++)
#pragma unroll
            for (int c = 0; c < 4; c++) acc[gt][c] = 0.f;

        const unsigned hbase = cur * 1024;
#pragma unroll
        for (int ks = 0; ks < 8; ks++) {
            uint4 av = *(const uint4*)&hfrag[hbase + ks * 128 + lane * 4];
            unsigned a[4] = { av.x, av.y, av.z, av.w };
            if (ks < 6) {
#pragma unroll
                for (int gt = 0; gt < 4; gt++)
                    mma_bf16(acc[gt], a, wreg[(ks * 4 + gt) * 2],
                                         wreg[(ks * 4 + gt) * 2 + 1]);
            } else {
#pragma unroll
                for (int gt = 0; gt < 4; gt++) {
                    uint2 bfr = *(const uint2*)
                        &wfrag[(((w * 2 + (ks - 6)) * 4 + gt) * 32 + lane) * 2];
                    mma_bf16(acc[gt], a, bfr.x, bfr.y);
                }
            }
        }

        // ---- pointwise, batch m=g (acc cols 0,1) ----
        if (s < len0) {
            const float pi0 = acc[0][0] + gva[0].x, pi1 = acc[0][1] + gva[0].y;
            const float pf0 = acc[1][0] + gva[1].x, pf1 = acc[1][1] + gva[1].y;
            const float pg0 = acc[2][0] + gva[2].x, pg1 = acc[2][1] + gva[2].y;
            const float po0 = acc[3][0] + gva[3].x, po1 = acc[3][1] + gva[3].y;
            c00 = fmaf(sigm_fast(pf0), c00, sigm_fast(pi0) * tanh_fast(pg0));
            c01 = fmaf(sigm_fast(pf1), c01, sigm_fast(pi1) * tanh_fast(pg1));
            h00 = sigm_fast(po0) * tanh_fast(c00);
            h01 = sigm_fast(po1) * tanh_fast(c01);
            if (write_seq) {
                const int tt = dir ? (len0 - 1 - s) : s;
                *(float2*)&h1[((size_t)(bb + g) * TLEN + tt) * (2 * HID) + dir * HID + q0]
                    = make_float2(h00, h01);
            }
        }
        // ---- pointwise, batch m=g+8 (acc cols 2,3) ----
        if (s < len1) {
            const float pi0 = acc[0][2] + gvb[0].x, pi1 = acc[0][3] + gvb[0].y;
            const float pf0 = acc[1][2] + gvb[1].x, pf1 = acc[1][3] + gvb[1].y;
            const float pg0 = acc[2][2] + gvb[2].x, pg1 = acc[2][3] + gvb[2].y;
            const float po0 = acc[3][2] + gvb[3].x, po1 = acc[3][3] + gvb[3].y;
            c10 = fmaf(sigm_fast(pf0), c10, sigm_fast(pi0) * tanh_fast(pg0));
            c11 = fmaf(sigm_fast(pf1), c11, sigm_fast(pi1) * tanh_fast(pg1));
            h10 = sigm_fast(po0) * tanh_fast(c10);
            h11 = sigm_fast(po1) * tanh_fast(c11);
            if (write_seq) {
                const int tt = dir ? (len1 - 1 - s) : s;
                *(float2*)&h1[((size_t)(bb + g + 8) * TLEN + tt) * (2 * HID) + dir * HID + q0]
                    = make_float2(h10, h11);
            }
        }

        // ---- publish h (bf16x2) into the other buffer, A-frag order ----
        const unsigned obase = (cur ^ 1) * 1024 + ksp * 128 + lane * 4;
        hfrag[obase + regA]     = pack_bf16(h00, h01);
        hfrag[obase + regA + 1] = pack_bf16(h10, h11);
        __syncthreads();
        cur ^= 1;

#pragma unroll
        for (int gt = 0; gt < 4; gt++) { gva[gt] = gna[gt]; gvb[gt] = gnb[gt]; }
    }

    if (hT) {
        *(float2*)&hT[((size_t)(dir * BATCH + bb + g))     * HID + q0] = make_float2(h00, h01);
        *(float2*)&hT[((size_t)(dir * BATCH + bb + g + 8)) * HID + q0] = make_float2(h10, h11);
    }

    if (write_seq) {
        // zero-fill padded region (reference masks hs to zero at t >= len)
        for (int qq = 0; qq < 16; qq++) {
            const int b  = bb + qq;
            const int lq = lens[b];
            const int ntail = (TLEN - lq) * HID;
            for (int idx = tid; idx < ntail; idx += 512) {
                const int tt = lq + (idx >> 7);
                const int k  = idx & 127;
                h1[((size_t)b * TLEN + tt) * (2 * HID) + dir * HID + k] = 0.f;
            }
        }
    }
}

// ---------------------------------------------------------------------------
// FC + log_softmax.  h = concat([hT_backward, hT_forward]).
// ---------------------------------------------------------------------------
__global__ __launch_bounds__(32)
void fc_kernel(const float* __restrict__ HT,    // [2][256][128] (dir0=fwd, dir1=bwd)
               const float* __restrict__ Wfc,   // [12][256]
               const float* __restrict__ bfc,   // [12]
               float*       __restrict__ out)   // [256][12]
{
    const int b = blockIdx.x;
    const int c = threadIdx.x;
    float acc = 0.f;
    if (c < NCLS) {
        acc = bfc[c];
        const float* hb = HT + ((size_t)BATCH + b) * HID;  // backward (first half)
        const float* hf = HT + (size_t)b * HID;            // forward  (second half)
        const float* w  = Wfc + c * (2 * HID);
#pragma unroll 4
        for (int k = 0; k < HID; k++) acc = fmaf(w[k], hb[k], acc);
#pragma unroll 4
        for (int k = 0; k < HID; k++) acc = fmaf(w[HID + k], hf[k], acc);
    }
    float mx = (c < NCLS) ? acc : -3.4e38f;
#pragma unroll
    for (int o = 16; o; o >>= 1) mx = fmaxf(mx, __shfl_xor_sync(0xffffffffu, mx, o));
    float e = (c < NCLS) ? expf(acc - mx) : 0.f;
    float ssum = e;
#pragma unroll
    for (int o = 16; o; o >>= 1) ssum += __shfl_xor_sync(0xffffffffu, ssum, o);
    if (c < NCLS) out[b * NCLS + c] = acc - mx - logf(ssum);
}

// ---------------------------------------------------------------------------
// Launch
// ---------------------------------------------------------------------------
extern "C" void kernel_launch(void* const* d_in, const int* in_sizes, int n_in,
                              void* d_out, int out_size)
{
    const float* X    = (const float*)d_in[0];
    const int*   lens = (const int*)  d_in[1];
    const float* Wih0 = (const float*)d_in[2];
    const float* Whh0 = (const float*)d_in[3];
    const float* b0   = (const float*)d_in[4];
    const float* Wih1 = (const float*)d_in[5];
    const float* Whh1 = (const float*)d_in[6];
    const float* b1   = (const float*)d_in[7];
    const float* Wfc  = (const float*)d_in[8];
    const float* bfc  = (const float*)d_in[9];
    float* out = (float*)d_out;

    float *G0, *G1, *H1, *HT;
    cudaGetSymbolAddress((void**)&G0, g_G0);
    cudaGetSymbolAddress((void**)&G1, g_G1);
    cudaGetSymbolAddress((void**)&H1, g_H1);
    cudaGetSymbolAddress((void**)&HT, g_HT);

    cudaFuncSetAttribute(lstm_tc_kernel, cudaFuncAttributeMaxDynamicSharedMemorySize,
                         LSTM_TC_SMEM);

    dim3 gemm_grid(1024 / 128, MROWS / 128);   // 8 n-tiles x 1024 m-tiles

    // layer 0: input gates (tf32 TC), then bidirectional recurrence -> H1
    gate_gemm_tc<DIN><<<gemm_grid, 256>>>(X, Wih0, b0, lens, G0);
    lstm_tc_kernel<<<32, 512, LSTM_TC_SMEM>>>(G0, Whh0, lens, H1, nullptr, 1);

    // layer 1: input gates over H1 (tf32 TC), recurrence -> final hiddens
    gate_gemm_tc<2 * HID><<<gemm_grid, 256>>>(H1, Wih1, b1, lens, G1);
    lstm_tc_kernel<<<32, 512, LSTM_TC_SMEM>>>(G1, Whh1, lens, nullptr, HT, 0);

    // classifier head
    fc_kernel<<<BATCH, 32>>>(HT, Wfc, bfc, out);
}